// round 2
// baseline (speedup 1.0000x reference)
#include <cuda_runtime.h>
#include <cuda_fp16.h>
#include <cstdint>

#define NCTA     75
#define NTHREADS 256
#define HID      1200
#define BATCH    64
#define TSTEPS   512
#define KT_H     75     // 1200/16 k-tiles
#define NT       450    // 3600/8 n-tiles

// ---------------- static device scratch (no allocation) ----------------
__device__ uint2 g_Wih0p[NT * 2 * 32];        // [nt][kt(2)][lane]
__device__ uint2 g_Whh0p[NT * KT_H * 32];     // [nt][kt(75)][lane]
__device__ uint2 g_Wih1p[NT * KT_H * 32];
__device__ uint2 g_Whh1p[NT * KT_H * 32];
__device__ __align__(16) __half g_x16[TSTEPS * BATCH * 32];   // [t][b][32] (I=30 padded)
__device__ __align__(16) float  g_h0f[2][BATCH * HID];
__device__ __align__(16) __half g_h0h[2][BATCH * HID];
__device__ __align__(16) float  g_h1f[2][BATCH * HID];
__device__ __align__(16) __half g_h1h[2][BATCH * HID];
__device__ unsigned g_arr;
__device__ unsigned g_epoch;

// ---------------- prep kernels ----------------
__global__ void zero_state_kernel() {
    int idx = blockIdx.x * blockDim.x + threadIdx.x;
    if (idx < BATCH * HID) {
        g_h0f[0][idx] = 0.f; g_h0f[1][idx] = 0.f;
        g_h1f[0][idx] = 0.f; g_h1f[1][idx] = 0.f;
        __half z = __float2half(0.f);
        g_h0h[0][idx] = z; g_h0h[1][idx] = z;
        g_h1h[0][idx] = z; g_h1h[1][idx] = z;
    }
    if (idx == 0) { g_arr = 0u; g_epoch = 0u; }
}

// Pack W [3600, K] row-major fp32 -> fragment-ordered fp16.
// Layout: dst[(nt*KT + kt)*32 + lane] = {W[g][k0..k0+1], W[g][k0+2..k0+3]}
// where g = nt*8 + lane/4, k0 = kt*16 + (lane%4)*4.  (K-permuted to match the
// A-side uint2 load: a0 gets k0..k0+1, a2 gets k0+2..k0+3.)
__global__ void pack_w_kernel(const float* __restrict__ W, int K, int KT, int which) {
    int idx = blockIdx.x * blockDim.x + threadIdx.x;
    int total = NT * KT * 32;
    if (idx >= total) return;
    int lane = idx & 31;
    int kt   = (idx >> 5) % KT;
    int nt   = (idx >> 5) / KT;
    int g    = nt * 8 + (lane >> 2);
    int k0   = kt * 16 + (lane & 3) * 4;
    const float* src = W + (size_t)g * K;
    unsigned h[4];
#pragma unroll
    for (int c = 0; c < 4; ++c) {
        int k = k0 + c;
        float v = (k < K) ? src[k] : 0.f;
        h[c] = (unsigned)__half_as_ushort(__float2half_rn(v));
    }
    uint2 out;
    out.x = h[0] | (h[1] << 16);
    out.y = h[2] | (h[3] << 16);
    uint2* dst = (which == 0) ? g_Wih0p : (which == 1) ? g_Whh0p
               : (which == 2) ? g_Wih1p : g_Whh1p;
    dst[idx] = out;
}

// x [B=64][T=512][I=30] fp32 -> g_x16 [t][b][32] fp16, zero-padded
__global__ void conv_x_kernel(const float* __restrict__ x) {
    int idx = blockIdx.x * blockDim.x + threadIdx.x;
    if (idx >= TSTEPS * BATCH * 32) return;
    int i = idx & 31;
    int b = (idx >> 5) & 63;
    int t = idx >> 11;
    float v = (i < 30) ? x[((size_t)b * TSTEPS + t) * 30 + i] : 0.f;
    g_x16[idx] = __float2half_rn(v);
}

// ---------------- device helpers ----------------
__device__ __forceinline__ void mma_16816(float c[4],
    unsigned a0, unsigned a1, unsigned a2, unsigned a3, unsigned b0, unsigned b1) {
    asm volatile(
        "mma.sync.aligned.m16n8k16.row.col.f32.f16.f16.f32 "
        "{%0,%1,%2,%3},{%4,%5,%6,%7},{%8,%9},{%0,%1,%2,%3};"
        : "+f"(c[0]), "+f"(c[1]), "+f"(c[2]), "+f"(c[3])
        : "r"(a0), "r"(a1), "r"(a2), "r"(a3), "r"(b0), "r"(b1));
}

#define MMA_AB(C, W) mma_16816(C, va.x, vb.x, va.y, vb.y, (W).x, (W).y)

__device__ __forceinline__ float sigf(float x) {
    return __fdividef(1.f, 1.f + __expf(-x));
}
__device__ __forceinline__ float tanhf_fast(float x) {
    return __fdividef(2.f, 1.f + __expf(-2.f * x)) - 1.f;
}

__device__ __forceinline__ void gru_combine(
    const float cR[4], const float cZ[4], const float cIN[4], const float cHN[4],
    const float* __restrict__ bih, const float* __restrict__ bhh,
    const float* __restrict__ hprev, float* __restrict__ hnf,
    __half* __restrict__ hnh, int rA, int jA, float* outp)
{
    float br[2], bz[2], bi[2], bh[2];
#pragma unroll
    for (int c = 0; c < 2; ++c) {
        br[c] = __ldg(bih + jA + c)            + __ldg(bhh + jA + c);
        bz[c] = __ldg(bih + HID + jA + c)      + __ldg(bhh + HID + jA + c);
        bi[c] = __ldg(bih + 2 * HID + jA + c);
        bh[c] = __ldg(bhh + 2 * HID + jA + c);
    }
#pragma unroll
    for (int p = 0; p < 2; ++p) {
        int row  = rA + p * 8;
        int base = row * HID + jA;
        float2 hp = __ldcg((const float2*)(hprev + base));
        float hv[2];
#pragma unroll
        for (int c = 0; c < 2; ++c) {
            int i   = p * 2 + c;
            float r = sigf(cR[i] + br[c]);
            float z = sigf(cZ[i] + bz[c]);
            float n = tanhf_fast(cIN[i] + bi[c] + r * (cHN[i] + bh[c]));
            float hpv = c ? hp.y : hp.x;
            hv[c] = n + z * (hpv - n);
        }
        __stcg((float2*)(hnf + base), make_float2(hv[0], hv[1]));
        unsigned u = (unsigned)__half_as_ushort(__float2half_rn(hv[0]))
                   | ((unsigned)__half_as_ushort(__float2half_rn(hv[1])) << 16);
        asm volatile("st.global.cg.u32 [%0], %1;" :: "l"(hnh + base), "r"(u) : "memory");
        if (outp) *(float2*)(outp + base) = make_float2(hv[0], hv[1]);
    }
}

// ---------------- persistent GRU kernel ----------------
__global__ void __launch_bounds__(NTHREADS, 1) gru_persistent(
    const float* __restrict__ b_ih0, const float* __restrict__ b_hh0,
    const float* __restrict__ b_ih1, const float* __restrict__ b_hh1,
    float* __restrict__ out)
{
    const int cta  = blockIdx.x;
    const int tid  = threadIdx.x;
    const int wid  = tid >> 5;
    const int lane = tid & 31;
    const int mt   = wid & 3;        // m-tile: batches mt*16..mt*16+15
    const int nh   = wid >> 2;       // column half: 0 or 1
    const int g    = lane >> 2;
    const int tid4 = lane & 3;
    const int rA   = mt * 16 + g;                      // batch row (and rA+8)
    const int jA   = cta * 16 + nh * 8 + tid4 * 2;     // hidden col (and jA+1)
    const int ntR  = cta * 2 + nh;                     // gate-col n-tiles
    const int ntZ  = ntR + 150;
    const int ntN  = ntR + 300;

    const uint2* wih0R = &g_Wih0p[ntR * 2 * 32];
    const uint2* wih0Z = &g_Wih0p[ntZ * 2 * 32];
    const uint2* wih0N = &g_Wih0p[ntN * 2 * 32];
    const uint2* whh0R = &g_Whh0p[ntR * KT_H * 32];
    const uint2* whh0Z = &g_Whh0p[ntZ * KT_H * 32];
    const uint2* whh0N = &g_Whh0p[ntN * KT_H * 32];
    const uint2* wih1R = &g_Wih1p[ntR * KT_H * 32];
    const uint2* wih1Z = &g_Wih1p[ntZ * KT_H * 32];
    const uint2* wih1N = &g_Wih1p[ntN * KT_H * 32];
    const uint2* whh1R = &g_Whh1p[ntR * KT_H * 32];
    const uint2* whh1Z = &g_Whh1p[ntZ * KT_H * 32];
    const uint2* whh1N = &g_Whh1p[ntN * KT_H * 32];

    const int rowOffA = rA * 300 + tid4;        // uint2 units, stride 300/row
    const int rowOffB = (rA + 8) * 300 + tid4;

    for (int t = 0; t <= TSTEPS; ++t) {
        // ---------- layer 0, step t ----------
        if (t < TSTEPS) {
            float cR[4] = {0,0,0,0}, cZ[4] = {0,0,0,0};
            float cIN[4] = {0,0,0,0}, cHN[4] = {0,0,0,0};
            // gi0 = x_t @ W_ih0^T  (K = 32 padded)
            {
                const uint2* pA = (const uint2*)(g_x16 + (size_t)t * BATCH * 32);
#pragma unroll
                for (int kt = 0; kt < 2; ++kt) {
                    uint2 va = __ldg(&pA[rA * 8 + kt * 4 + tid4]);
                    uint2 vb = __ldg(&pA[(rA + 8) * 8 + kt * 4 + tid4]);
                    uint2 w;
                    w = __ldg(&wih0R[kt * 32 + lane]); MMA_AB(cR, w);
                    w = __ldg(&wih0Z[kt * 32 + lane]); MMA_AB(cZ, w);
                    w = __ldg(&wih0N[kt * 32 + lane]); MMA_AB(cIN, w);
                }
            }
            // gh0 = h0 @ W_hh0^T
            {
                const uint2* pH = (const uint2*)g_h0h[t & 1];
#pragma unroll 5
                for (int kt = 0; kt < KT_H; ++kt) {
                    uint2 va = __ldcg(&pH[rowOffA + kt * 4]);
                    uint2 vb = __ldcg(&pH[rowOffB + kt * 4]);
                    uint2 w;
                    w = __ldg(&whh0R[kt * 32 + lane]); MMA_AB(cR, w);
                    w = __ldg(&whh0Z[kt * 32 + lane]); MMA_AB(cZ, w);
                    w = __ldg(&whh0N[kt * 32 + lane]); MMA_AB(cHN, w);
                }
            }
            gru_combine(cR, cZ, cIN, cHN, b_ih0, b_hh0,
                        g_h0f[t & 1], g_h0f[(t + 1) & 1], g_h0h[(t + 1) & 1],
                        rA, jA, (t == TSTEPS - 1) ? out : nullptr);
        }
        // ---------- layer 1, step t-1 ----------
        if (t >= 1) {
            float cR[4] = {0,0,0,0}, cZ[4] = {0,0,0,0};
            float cIN[4] = {0,0,0,0}, cHN[4] = {0,0,0,0};
            // gi1 = out0[t-1] @ W_ih1^T   (out0[t-1] lives in g_h0h[t&1])
            {
                const uint2* pA = (const uint2*)g_h0h[t & 1];
#pragma unroll 5
                for (int kt = 0; kt < KT_H; ++kt) {
                    uint2 va = __ldcg(&pA[rowOffA + kt * 4]);
                    uint2 vb = __ldcg(&pA[rowOffB + kt * 4]);
                    uint2 w;
                    w = __ldg(&wih1R[kt * 32 + lane]); MMA_AB(cR, w);
                    w = __ldg(&wih1Z[kt * 32 + lane]); MMA_AB(cZ, w);
                    w = __ldg(&wih1N[kt * 32 + lane]); MMA_AB(cIN, w);
                }
            }
            // gh1 = h1[t-2] @ W_hh1^T
            {
                const uint2* pH = (const uint2*)g_h1h[(t - 1) & 1];
#pragma unroll 5
                for (int kt = 0; kt < KT_H; ++kt) {
                    uint2 va = __ldcg(&pH[rowOffA + kt * 4]);
                    uint2 vb = __ldcg(&pH[rowOffB + kt * 4]);
                    uint2 w;
                    w = __ldg(&whh1R[kt * 32 + lane]); MMA_AB(cR, w);
                    w = __ldg(&whh1Z[kt * 32 + lane]); MMA_AB(cZ, w);
                    w = __ldg(&whh1N[kt * 32 + lane]); MMA_AB(cHN, w);
                }
            }
            gru_combine(cR, cZ, cIN, cHN, b_ih1, b_hh1,
                        g_h1f[(t - 1) & 1], g_h1f[t & 1], g_h1h[t & 1],
                        rA, jA, (t == TSTEPS) ? out + BATCH * HID : nullptr);
        }
        // ---------- grid-wide barrier (epoch t+1) ----------
        __syncthreads();
        if (tid == 0) {
            __threadfence();
            unsigned a = atomicAdd(&g_arr, 1u);
            if (a == NCTA - 1) {
                g_arr = 0u;
                __threadfence();
                atomicExch(&g_epoch, (unsigned)(t + 1));
            } else {
                unsigned e;
                while (true) {
                    asm volatile("ld.global.cg.u32 %0,[%1];" : "=r"(e) : "l"(&g_epoch));
                    if (e >= (unsigned)(t + 1)) break;
                    __nanosleep(32);
                }
            }
        }
        __syncthreads();
    }
}

// ---------------- launch ----------------
extern "C" void kernel_launch(void* const* d_in, const int* in_sizes, int n_in,
                              void* d_out, int out_size) {
    const float* x     = (const float*)d_in[0];
    const float* W_ih0 = (const float*)d_in[1];
    const float* W_hh0 = (const float*)d_in[2];
    const float* b_ih0 = (const float*)d_in[3];
    const float* b_hh0 = (const float*)d_in[4];
    const float* W_ih1 = (const float*)d_in[5];
    const float* W_hh1 = (const float*)d_in[6];
    const float* b_ih1 = (const float*)d_in[7];
    const float* b_hh1 = (const float*)d_in[8];
    float* out = (float*)d_out;

    // state reset (must run every launch: graph replays reuse device globals)
    zero_state_kernel<<<(BATCH * HID + 255) / 256, 256>>>();

    // pack weights to fragment-ordered fp16
    {
        int n0 = NT * 2 * 32;
        pack_w_kernel<<<(n0 + 255) / 256, 256>>>(W_ih0, 30,   2,    0);
        int n1 = NT * KT_H * 32;
        pack_w_kernel<<<(n1 + 255) / 256, 256>>>(W_hh0, HID, KT_H, 1);
        pack_w_kernel<<<(n1 + 255) / 256, 256>>>(W_ih1, HID, KT_H, 2);
        pack_w_kernel<<<(n1 + 255) / 256, 256>>>(W_hh1, HID, KT_H, 3);
    }
    // convert x to fp16 [t][b][32]
    {
        int nx = TSTEPS * BATCH * 32;
        conv_x_kernel<<<(nx + 255) / 256, 256>>>(x);
    }
    // persistent fused 2-layer GRU
    gru_persistent<<<NCTA, NTHREADS>>>(b_ih0, b_hh0, b_ih1, b_hh1, out);
}

// round 3
// speedup vs baseline: 1.2234x; 1.2234x over previous
#include <cuda_runtime.h>
#include <cuda_fp16.h>
#include <cstdint>

#define NCTA     75
#define NTHREADS 256
#define HID      1200
#define BATCH    64
#define TSTEPS   512
#define KT_H     75      // 1200/16 k-tiles
#define NT       450     // 3600/8 n-tiles (for W_ih0 packing)
#define CK       15      // k-tiles per smem chunk
#define NCHUNK   5       // 75/15
#define SLOTS    18      // 3 matrices x 3 gates x 2 col-halves
#define CHUNK_U2 (CK * SLOTS * 32)          // uint2 per chunk = 8640
#define CHUNK_BYTES (CHUNK_U2 * 8)          // 69120
#define SMEM_BYTES (2 * CHUNK_BYTES)        // 138240

// ---------------- static device scratch (no allocation) ----------------
__device__ uint2 g_Wih0p[NT * 2 * 32];                       // x-weights, frag order
__device__ uint2 g_Wpk[(size_t)NCTA * KT_H * SLOTS * 32];    // [cta][kt][slot][lane]
__device__ __align__(16) __half g_x16[TSTEPS * BATCH * 32];  // [t][b][32]
__device__ __align__(16) float  g_h0f[2][BATCH * HID];
__device__ __align__(16) __half g_h0h[2][BATCH * HID];
__device__ __align__(16) float  g_h1f[2][BATCH * HID];
__device__ __align__(16) __half g_h1h[2][BATCH * HID];
__device__ unsigned g_arr;
__device__ unsigned g_epoch;

// ---------------- prep kernels ----------------
__global__ void zero_state_kernel() {
    int idx = blockIdx.x * blockDim.x + threadIdx.x;
    if (idx < BATCH * HID) {
        g_h0f[0][idx] = 0.f; g_h0f[1][idx] = 0.f;
        g_h1f[0][idx] = 0.f; g_h1f[1][idx] = 0.f;
        __half z = __float2half(0.f);
        g_h0h[0][idx] = z; g_h0h[1][idx] = z;
        g_h1h[0][idx] = z; g_h1h[1][idx] = z;
    }
    if (idx == 0) { g_arr = 0u; g_epoch = 0u; }
}

// Pack W_ih0 [3600,30] -> frag order [nt][kt(2)][lane], K padded to 32.
__global__ void pack_wih0_kernel(const float* __restrict__ W) {
    int idx = blockIdx.x * blockDim.x + threadIdx.x;
    if (idx >= NT * 2 * 32) return;
    int lane = idx & 31;
    int kt   = (idx >> 5) & 1;
    int nt   = idx >> 6;
    int g    = nt * 8 + (lane >> 2);
    int k0   = kt * 16 + (lane & 3) * 4;
    const float* src = W + (size_t)g * 30;
    unsigned h[4];
#pragma unroll
    for (int c = 0; c < 4; ++c) {
        int k = k0 + c;
        float v = (k < 30) ? src[k] : 0.f;
        h[c] = (unsigned)__half_as_ushort(__float2half_rn(v));
    }
    uint2 o; o.x = h[0] | (h[1] << 16); o.y = h[2] | (h[3] << 16);
    g_Wih0p[idx] = o;
}

// Pack the three big [3600,1200] matrices into unified per-CTA chunk layout:
// index = ((cta*75 + kt)*18 + s)*32 + lane, s = mat*6 + gate*2 + nh
// mat: 0=W_hh0, 1=W_ih1, 2=W_hh1
__global__ void pack_big_kernel(const float* __restrict__ Whh0,
                                const float* __restrict__ Wih1,
                                const float* __restrict__ Whh1) {
    long idx = (long)blockIdx.x * blockDim.x + threadIdx.x;
    const long total = (long)NCTA * KT_H * SLOTS * 32;
    if (idx >= total) return;
    int lane = (int)(idx & 31);
    long r1  = idx >> 5;
    int s    = (int)(r1 % SLOTS);
    long r2  = r1 / SLOTS;
    int kt   = (int)(r2 % KT_H);
    int cta  = (int)(r2 / KT_H);
    int mat  = s / 6, rem = s % 6, gate = rem >> 1, nh = rem & 1;
    int row  = gate * 1200 + cta * 16 + nh * 8 + (lane >> 2);
    int k0   = kt * 16 + (lane & 3) * 4;
    const float* W = (mat == 0) ? Whh0 : (mat == 1) ? Wih1 : Whh1;
    const float* src = W + (size_t)row * HID + k0;
    unsigned h[4];
#pragma unroll
    for (int c = 0; c < 4; ++c)
        h[c] = (unsigned)__half_as_ushort(__float2half_rn(src[c]));
    uint2 o; o.x = h[0] | (h[1] << 16); o.y = h[2] | (h[3] << 16);
    g_Wpk[idx] = o;
}

// x [B][T][30] fp32 -> g_x16 [t][b][32] fp16, zero-padded
__global__ void conv_x_kernel(const float* __restrict__ x) {
    int idx = blockIdx.x * blockDim.x + threadIdx.x;
    if (idx >= TSTEPS * BATCH * 32) return;
    int i = idx & 31;
    int b = (idx >> 5) & 63;
    int t = idx >> 11;
    float v = (i < 30) ? x[((size_t)b * TSTEPS + t) * 30 + i] : 0.f;
    g_x16[idx] = __float2half_rn(v);
}

// ---------------- device helpers ----------------
__device__ __forceinline__ void mma_16816(float c[4],
    unsigned a0, unsigned a1, unsigned a2, unsigned a3, unsigned b0, unsigned b1) {
    asm volatile(
        "mma.sync.aligned.m16n8k16.row.col.f32.f16.f16.f32 "
        "{%0,%1,%2,%3},{%4,%5,%6,%7},{%8,%9},{%0,%1,%2,%3};"
        : "+f"(c[0]), "+f"(c[1]), "+f"(c[2]), "+f"(c[3])
        : "r"(a0), "r"(a1), "r"(a2), "r"(a3), "r"(b0), "r"(b1));
}
#define MMA_W(C, VA, VB, W) mma_16816(C, (VA).x, (VB).x, (VA).y, (VB).y, (W).x, (W).y)

__device__ __forceinline__ void cpa16(void* s, const void* g) {
    unsigned sa = (unsigned)__cvta_generic_to_shared(s);
    asm volatile("cp.async.cg.shared.global [%0],[%1],16;" :: "r"(sa), "l"(g));
}
__device__ __forceinline__ void cp_commit() { asm volatile("cp.async.commit_group;"); }
template <int N> __device__ __forceinline__ void cp_wait() {
    asm volatile("cp.async.wait_group %0;" :: "n"(N));
}

__device__ __forceinline__ float sigf(float x) {
    return __fdividef(1.f, 1.f + __expf(-x));
}
__device__ __forceinline__ float tanhf_fast(float x) {
    return __fdividef(2.f, 1.f + __expf(-2.f * x)) - 1.f;
}

__device__ __forceinline__ void gru_combine(
    const float cR[4], const float cZ[4], const float cIN[4], const float cHN[4],
    const float* __restrict__ bih, const float* __restrict__ bhh,
    const float* __restrict__ hprev, float* __restrict__ hnf,
    __half* __restrict__ hnh, int rA, int jA, float* outp)
{
    float br[2], bz[2], bi[2], bh[2];
#pragma unroll
    for (int c = 0; c < 2; ++c) {
        br[c] = __ldg(bih + jA + c)            + __ldg(bhh + jA + c);
        bz[c] = __ldg(bih + HID + jA + c)      + __ldg(bhh + HID + jA + c);
        bi[c] = __ldg(bih + 2 * HID + jA + c);
        bh[c] = __ldg(bhh + 2 * HID + jA + c);
    }
#pragma unroll
    for (int p = 0; p < 2; ++p) {
        int base = (rA + p * 8) * HID + jA;
        float2 hp = __ldcg((const float2*)(hprev + base));
        float hv[2];
#pragma unroll
        for (int c = 0; c < 2; ++c) {
            int i   = p * 2 + c;
            float r = sigf(cR[i] + br[c]);
            float z = sigf(cZ[i] + bz[c]);
            float n = tanhf_fast(cIN[i] + bi[c] + r * (cHN[i] + bh[c]));
            float hpv = c ? hp.y : hp.x;
            hv[c] = n + z * (hpv - n);
        }
        __stcg((float2*)(hnf + base), make_float2(hv[0], hv[1]));
        unsigned u = (unsigned)__half_as_ushort(__float2half_rn(hv[0]))
                   | ((unsigned)__half_as_ushort(__float2half_rn(hv[1])) << 16);
        asm volatile("st.global.cg.u32 [%0], %1;" :: "l"(hnh + base), "r"(u) : "memory");
        if (outp) *(float2*)(outp + base) = make_float2(hv[0], hv[1]);
    }
}

// ---------------- persistent fused 2-layer GRU ----------------
__global__ void __launch_bounds__(NTHREADS, 1) gru_persistent(
    const float* __restrict__ b_ih0, const float* __restrict__ b_hh0,
    const float* __restrict__ b_ih1, const float* __restrict__ b_hh1,
    float* __restrict__ out)
{
    extern __shared__ uint2 smw[];   // [2][CK][SLOTS][32]

    const int cta  = blockIdx.x;
    const int tid  = threadIdx.x;
    const int wid  = tid >> 5;
    const int lane = tid & 31;
    const int mt   = wid & 3;
    const int nh   = wid >> 2;
    const int g    = lane >> 2;
    const int tid4 = lane & 3;
    const int rA   = mt * 16 + g;
    const int jA   = cta * 16 + nh * 8 + tid4 * 2;

    // x-weights (tiny)
    const int ntR = cta * 2 + nh;
    const uint2* wih0R = &g_Wih0p[ntR * 2 * 32];
    const uint2* wih0Z = &g_Wih0p[(ntR + 150) * 2 * 32];
    const uint2* wih0N = &g_Wih0p[(ntR + 300) * 2 * 32];

    const int rowOffA = rA * 300 + tid4;        // uint2 units (1200 halves/row)
    const int rowOffB = (rA + 8) * 300 + tid4;

    const uint2* gW = g_Wpk + (size_t)cta * KT_H * SLOTS * 32;

    for (int r = 0; r <= TSTEPS; ++r) {
        float cR0[4] = {0,0,0,0}, cZ0[4] = {0,0,0,0}, cIN0[4] = {0,0,0,0}, cHN0[4] = {0,0,0,0};
        float cR1[4] = {0,0,0,0}, cZ1[4] = {0,0,0,0}, cIN1[4] = {0,0,0,0}, cHN1[4] = {0,0,0,0};

        const uint2* pH0 = (const uint2*)g_h0h[r & 1];        // h0[r-1] / out0 feed
        const uint2* pH1 = (const uint2*)g_h1h[(r + 1) & 1];  // h1[r-2]

        // ---- gi0 = x_r @ W_ih0^T (K=32 padded), skip at r==TSTEPS ----
        if (r < TSTEPS) {
            const uint2* pA = (const uint2*)(g_x16 + (size_t)r * BATCH * 32);
#pragma unroll
            for (int kt = 0; kt < 2; ++kt) {
                uint2 va = __ldg(&pA[rA * 8 + kt * 4 + tid4]);
                uint2 vb = __ldg(&pA[(rA + 8) * 8 + kt * 4 + tid4]);
                uint2 w;
                w = __ldg(&wih0R[kt * 32 + lane]); MMA_W(cR0, va, vb, w);
                w = __ldg(&wih0Z[kt * 32 + lane]); MMA_W(cZ0, va, vb, w);
                w = __ldg(&wih0N[kt * 32 + lane]); MMA_W(cIN0, va, vb, w);
            }
        }

        // ---- fused k-loop over 3 big matrices, smem-staged weights ----
        // prologue: stage chunk 0
        {
            const uint2* src = gW;
            for (int i = tid; i < CHUNK_U2 / 2; i += NTHREADS)
                cpa16(&smw[i * 2], &src[i * 2]);
            cp_commit();
        }
#pragma unroll 1
        for (int c = 0; c < NCHUNK; ++c) {
            if (c + 1 < NCHUNK) {
                const uint2* src = gW + (size_t)(c + 1) * CHUNK_U2;
                uint2* dst = smw + ((c + 1) & 1) * CHUNK_U2;
                for (int i = tid; i < CHUNK_U2 / 2; i += NTHREADS)
                    cpa16(&dst[i * 2], &src[i * 2]);
                cp_commit();
                cp_wait<1>();
            } else {
                cp_wait<0>();
            }
            __syncthreads();

            const uint2* wb = smw + (c & 1) * CHUNK_U2 + lane;
#pragma unroll 3
            for (int ktl = 0; ktl < CK; ++ktl) {
                const int kt = c * CK + ktl;
                uint2 a0A = __ldcg(&pH0[rowOffA + kt * 4]);
                uint2 a0B = __ldcg(&pH0[rowOffB + kt * 4]);
                uint2 a1A = __ldcg(&pH1[rowOffA + kt * 4]);
                uint2 a1B = __ldcg(&pH1[rowOffB + kt * 4]);
                const uint2* wk = wb + ktl * (SLOTS * 32);
                uint2 w;
                // mat0 = W_hh0 (A = h0)
                w = wk[(0 + nh) * 32];      MMA_W(cR0, a0A, a0B, w);
                w = wk[(2 + nh) * 32];      MMA_W(cZ0, a0A, a0B, w);
                w = wk[(4 + nh) * 32];      MMA_W(cHN0, a0A, a0B, w);
                // mat1 = W_ih1 (A = h0)
                w = wk[(6 + nh) * 32];      MMA_W(cR1, a0A, a0B, w);
                w = wk[(8 + nh) * 32];      MMA_W(cZ1, a0A, a0B, w);
                w = wk[(10 + nh) * 32];     MMA_W(cIN1, a0A, a0B, w);
                // mat2 = W_hh1 (A = h1)
                w = wk[(12 + nh) * 32];     MMA_W(cR1, a1A, a1B, w);
                w = wk[(14 + nh) * 32];     MMA_W(cZ1, a1A, a1B, w);
                w = wk[(16 + nh) * 32];     MMA_W(cHN1, a1A, a1B, w);
            }
            __syncthreads();
        }

        // ---- combines ----
        if (r < TSTEPS) {
            gru_combine(cR0, cZ0, cIN0, cHN0, b_ih0, b_hh0,
                        g_h0f[r & 1], g_h0f[(r + 1) & 1], g_h0h[(r + 1) & 1],
                        rA, jA, (r == TSTEPS - 1) ? out : nullptr);
        }
        if (r >= 1) {
            gru_combine(cR1, cZ1, cIN1, cHN1, b_ih1, b_hh1,
                        g_h1f[(r + 1) & 1], g_h1f[r & 1], g_h1h[r & 1],
                        rA, jA, (r == TSTEPS) ? out + BATCH * HID : nullptr);
        }

        // ---- grid-wide barrier (epoch r+1) ----
        __threadfence();
        __syncthreads();
        if (tid == 0) {
            unsigned a = atomicAdd(&g_arr, 1u);
            if (a == NCTA - 1) {
                g_arr = 0u;
                __threadfence();
                atomicExch(&g_epoch, (unsigned)(r + 1));
            } else {
                unsigned e;
                while (true) {
                    asm volatile("ld.global.cg.u32 %0,[%1];" : "=r"(e) : "l"(&g_epoch));
                    if (e >= (unsigned)(r + 1)) break;
                    __nanosleep(32);
                }
            }
        }
        __syncthreads();
    }
}

// ---------------- launch ----------------
extern "C" void kernel_launch(void* const* d_in, const int* in_sizes, int n_in,
                              void* d_out, int out_size) {
    const float* x     = (const float*)d_in[0];
    const float* W_ih0 = (const float*)d_in[1];
    const float* W_hh0 = (const float*)d_in[2];
    const float* b_ih0 = (const float*)d_in[3];
    const float* b_hh0 = (const float*)d_in[4];
    const float* W_ih1 = (const float*)d_in[5];
    const float* W_hh1 = (const float*)d_in[6];
    const float* b_ih1 = (const float*)d_in[7];
    const float* b_hh1 = (const float*)d_in[8];
    float* out = (float*)d_out;

    cudaFuncSetAttribute(gru_persistent,
                         cudaFuncAttributeMaxDynamicSharedMemorySize, SMEM_BYTES);

    zero_state_kernel<<<(BATCH * HID + 255) / 256, 256>>>();

    pack_wih0_kernel<<<(NT * 2 * 32 + 255) / 256, 256>>>(W_ih0);
    {
        long total = (long)NCTA * KT_H * SLOTS * 32;
        pack_big_kernel<<<(int)((total + 255) / 256), 256>>>(W_hh0, W_ih1, W_hh1);
    }
    conv_x_kernel<<<(TSTEPS * BATCH * 32 + 255) / 256, 256>>>(x);

    gru_persistent<<<NCTA, NTHREADS, SMEM_BYTES>>>(b_ih0, b_hh0, b_ih1, b_hh1, out);
}

// round 4
// speedup vs baseline: 1.7148x; 1.4017x over previous
#include <cuda_runtime.h>
#include <cuda_fp16.h>
#include <cstdint>

#define NCTA   145
#define NTH    256
#define HIDN   1200
#define BT     64
#define TS     512
#define ROUNDS 514
#define SM_XW  172800         // x-weight region (L0 only), inside weight region
#define SM_A   192000         // A-stage base (3 buffers)
#define ABUF   11264          // 64 rows * 176 bytes
#define ASTRIDE 176
#define SMEM_TOTAL 225792     // 192000 + 3*11264

// ---------------- static device scratch ----------------
__device__ uint2 g_Wpk[(size_t)NCTA * 12 * 75 * 32];   // resident-weight pack
__device__ uint2 g_Wxp[50 * 9 * 2 * 32];               // L0 x-weights pack
__device__ __align__(16) __half g_x16[TS * BT * 32];   // [t][b][32]
__device__ __align__(16) __half g_h0h[2][BT * HIDN];
__device__ __align__(16) __half g_h1h[2][BT * HIDN];
__device__ float g_gi1[2][3600 * BT];                  // [par][gate-row][b]
__device__ unsigned g_arr;
__device__ unsigned g_epoch;

// ---------------- prep kernels ----------------
__global__ void zero_state_kernel() {
    int idx = blockIdx.x * blockDim.x + threadIdx.x;
    if (idx < BT * HIDN) {
        __half z = __float2half(0.f);
        g_h0h[0][idx] = z; g_h0h[1][idx] = z;
        g_h1h[0][idx] = z; g_h1h[1][idx] = z;
    }
    if (idx == 0) { g_arr = 0u; g_epoch = 0u; }
}

// Pack per-CTA resident weights: [(cta*12+s)*75+kt]*32+lane
__global__ void pack_res_kernel(const float* __restrict__ Whh0,
                                const float* __restrict__ Wih1,
                                const float* __restrict__ Whh1) {
    long idx = (long)blockIdx.x * blockDim.x + threadIdx.x;
    const long total = (long)NCTA * 12 * 75 * 32;
    if (idx >= total) return;
    int lane = (int)(idx & 31);
    long u = idx >> 5;
    int kt = (int)(u % 75);
    long v = u / 75;
    int s = (int)(v % 12);
    int cta = (int)(v / 12);
    const float* W;
    int row0;
    if (cta < 50) {
        if (s >= 9) return;
        W = Whh0; row0 = (s / 3) * 1200 + cta * 24 + (s % 3) * 8;
    } else if (cta < 95) {
        if (s >= 10) return;
        W = Wih1; row0 = ((cta - 50) * 10 + s) * 8;
    } else {
        if (s >= 9) return;
        W = Whh1; row0 = (s / 3) * 1200 + (cta - 95) * 24 + (s % 3) * 8;
    }
    int row = row0 + (lane >> 2);
    int k0 = kt * 16 + (lane & 3) * 4;
    const float* src = W + (size_t)row * HIDN + k0;
    unsigned h[4];
#pragma unroll
    for (int c = 0; c < 4; ++c)
        h[c] = (unsigned)__half_as_ushort(__float2half_rn(src[c]));
    uint2 o; o.x = h[0] | (h[1] << 16); o.y = h[2] | (h[3] << 16);
    g_Wpk[idx] = o;
}

// Pack W_ih0 slices for L0 CTAs: [((cta*9+s)*2+kt)*32+lane], K=30 padded to 32
__global__ void pack_x_kernel(const float* __restrict__ Wih0) {
    int idx = blockIdx.x * blockDim.x + threadIdx.x;
    if (idx >= 50 * 9 * 2 * 32) return;
    int lane = idx & 31;
    int kt = (idx >> 5) & 1;
    int u = idx >> 6;
    int s = u % 9;
    int cta = u / 9;
    int row = (s / 3) * 1200 + cta * 24 + (s % 3) * 8 + (lane >> 2);
    int k0 = kt * 16 + (lane & 3) * 4;
    unsigned h[4];
#pragma unroll
    for (int c = 0; c < 4; ++c) {
        int k = k0 + c;
        float v = (k < 30) ? Wih0[(size_t)row * 30 + k] : 0.f;
        h[c] = (unsigned)__half_as_ushort(__float2half_rn(v));
    }
    uint2 o; o.x = h[0] | (h[1] << 16); o.y = h[2] | (h[3] << 16);
    g_Wxp[idx] = o;
}

// x [B][T][30] fp32 -> g_x16 [t][b][32] fp16
__global__ void conv_x_kernel(const float* __restrict__ x) {
    int idx = blockIdx.x * blockDim.x + threadIdx.x;
    if (idx >= TS * BT * 32) return;
    int i = idx & 31;
    int b = (idx >> 5) & 63;
    int t = idx >> 11;
    float v = (i < 30) ? x[((size_t)b * TS + t) * 30 + i] : 0.f;
    g_x16[idx] = __float2half_rn(v);
}

// ---------------- device helpers ----------------
__device__ __forceinline__ void mma_16816(float c[4],
    unsigned a0, unsigned a1, unsigned a2, unsigned a3, unsigned b0, unsigned b1) {
    asm volatile(
        "mma.sync.aligned.m16n8k16.row.col.f32.f16.f16.f32 "
        "{%0,%1,%2,%3},{%4,%5,%6,%7},{%8,%9},{%0,%1,%2,%3};"
        : "+f"(c[0]), "+f"(c[1]), "+f"(c[2]), "+f"(c[3])
        : "r"(a0), "r"(a1), "r"(a2), "r"(a3), "r"(b0), "r"(b1));
}
__device__ __forceinline__ void cpa16(void* s, const void* g) {
    unsigned sa = (unsigned)__cvta_generic_to_shared(s);
    asm volatile("cp.async.cg.shared.global [%0],[%1],16;" :: "r"(sa), "l"(g));
}
__device__ __forceinline__ void cp_commit() { asm volatile("cp.async.commit_group;"); }
template <int N> __device__ __forceinline__ void cp_wait() {
    asm volatile("cp.async.wait_group %0;" :: "n"(N));
}
__device__ __forceinline__ float sigf(float x) {
    return __fdividef(1.f, 1.f + __expf(-x));
}
__device__ __forceinline__ float tanhf_fast(float x) {
    return __fdividef(2.f, 1.f + __expf(-2.f * x)) - 1.f;
}
__device__ __forceinline__ void sth16(__half* p, float v) {
    unsigned short u = __half_as_ushort(__float2half_rn(v));
    asm volatile("st.global.cg.u16 [%0], %1;" :: "l"(p), "h"(u) : "memory");
}

// ---------------- persistent kernel ----------------
__global__ void __launch_bounds__(NTH, 1) gru_main(
    const float* __restrict__ b_ih0, const float* __restrict__ b_hh0,
    const float* __restrict__ b_ih1, const float* __restrict__ b_hh1,
    float* __restrict__ out)
{
    extern __shared__ char sm[];
    const int cta  = blockIdx.x;
    const int tid  = threadIdx.x;
    const int wid  = tid >> 5;
    const int lane = tid & 31;
    const int mw   = wid >> 2;       // 0..1 (pair of m-tiles)
    const int nw   = wid & 3;        // 0..3 (n-split)
    const int g    = lane >> 2;
    const int tid4 = lane & 3;
    const int cls  = (cta < 50) ? 0 : (cta < 95) ? 1 : 2;

    // ---- load resident weights (once) ----
    const int nbig = (cls == 1) ? 10 : 9;
    {
        const uint2* wsrc = g_Wpk + (size_t)cta * 12 * 75 * 32;
        int n16 = nbig * 1200;               // 16B units (2400 u2 per slot)
        for (int i = tid; i < n16; i += NTH)
            cpa16(sm + i * 16, wsrc + i * 2);
        if (cls == 0) {
            const uint2* xs = g_Wxp + cta * 576;
            for (int i = tid; i < 288; i += NTH)
                cpa16(sm + SM_XW + i * 16, xs + i * 2);
        }
        cp_commit();
        cp_wait<0>();
        __syncthreads();
    }

    // ---- warp slot assignment ----
    int slot0, nmy;
    if (cls == 0) { slot0 = nw * 3; nmy = (nw < 3) ? 3 : 0; }
    else if (cls == 1) { nmy = (nw < 2) ? 3 : 2; slot0 = (nw < 2) ? nw * 3 : 6 + (nw - 2) * 2; }
    else { nmy = (nw < 2) ? 3 : ((nw == 2) ? 2 : 1); slot0 = (nw < 2) ? nw * 3 : ((nw == 2) ? 6 : 8); }

    // ---- combine-side setup (L0 / H1) ----
    const int jbase = (cls == 0) ? cta * 24 : (cls == 2) ? (cta - 95) * 24 : 0;
    float bias[6][4];
    float hprev[6];
    if (cls != 1) {
        const float* bi = (cls == 0) ? b_ih0 : b_ih1;
        const float* bh = (cls == 0) ? b_hh0 : b_hh1;
#pragma unroll
        for (int q = 0; q < 6; ++q) {
            int pi = q * 256 + tid;
            int jg = jbase + (pi >> 6);
            bias[q][0] = __ldg(bi + jg) + __ldg(bh + jg);
            bias[q][1] = __ldg(bi + 1200 + jg) + __ldg(bh + 1200 + jg);
            bias[q][2] = __ldg(bi + 2400 + jg);
            bias[q][3] = __ldg(bh + 2400 + jg);
            hprev[q] = 0.f;
        }
    }

    float* pre = (float*)(sm + SM_A);

    for (int r = 0; r < ROUNDS; ++r) {
        const bool act = (cls == 0) ? (r < TS)
                        : (cls == 1) ? (r >= 1 && r <= TS)
                                     : (r >= 2);
        if (act) {
            float acc[3][2][4];
#pragma unroll
            for (int s = 0; s < 3; ++s)
#pragma unroll
                for (int q = 0; q < 2; ++q)
#pragma unroll
                    for (int c = 0; c < 4; ++c) acc[s][q][c] = 0.f;

            const __half* Asrc = (cls == 2) ? g_h1h[(r + 1) & 1] : g_h0h[(r + 1) & 1];

            // ---- L0 x-GEMM: gi0 R/Z into acc (nw0/nw1), i_n into nw3's acc ----
            if (cls == 0) {
                const uint2* pA = (const uint2*)(g_x16 + (size_t)r * BT * 32);
#pragma unroll
                for (int kt2 = 0; kt2 < 2; ++kt2) {
                    uint2 a[2][2];
#pragma unroll
                    for (int q = 0; q < 2; ++q) {
                        int rA = (mw * 2 + q) * 16 + g;
                        a[q][0] = __ldg(&pA[rA * 8 + kt2 * 4 + tid4]);
                        a[q][1] = __ldg(&pA[(rA + 8) * 8 + kt2 * 4 + tid4]);
                    }
                    int xbase = (nw == 3) ? 6 : nw * 3;   // nw2 skipped below
#pragma unroll
                    for (int si = 0; si < 3; ++si) {
                        if (nw == 2) break;
                        uint2 w = *(const uint2*)(sm + SM_XW +
                                   (((xbase + si) * 2 + kt2) * 32 + lane) * 8);
#pragma unroll
                        for (int q = 0; q < 2; ++q)
                            mma_16816(acc[si][q], a[q][0].x, a[q][1].x,
                                      a[q][0].y, a[q][1].y, w.x, w.y);
                    }
                }
            }

            // ---- k-loop: 15 chunks of 5 k-tiles, 3-deep cp.async pipeline ----
            {
                // stage chunks 0 and 1
#pragma unroll
                for (int pc = 0; pc < 2; ++pc) {
                    char* dst = sm + SM_A + pc * ABUF;
                    const __half* src = Asrc + pc * 80;
                    for (int i = tid; i < 640; i += NTH) {
                        int row = i / 10, seg = i % 10;
                        cpa16(dst + row * ASTRIDE + seg * 16,
                              src + (size_t)row * HIDN + seg * 8);
                    }
                    cp_commit();
                }
#pragma unroll 1
                for (int ck = 0; ck < 15; ++ck) {
                    if (ck + 2 < 15) {
                        char* dst = sm + SM_A + ((ck + 2) % 3) * ABUF;
                        const __half* src = Asrc + (ck + 2) * 80;
                        for (int i = tid; i < 640; i += NTH) {
                            int row = i / 10, seg = i % 10;
                            cpa16(dst + row * ASTRIDE + seg * 16,
                                  src + (size_t)row * HIDN + seg * 8);
                        }
                    }
                    cp_commit();
                    cp_wait<2>();
                    __syncthreads();

                    if (nmy > 0) {
                        const char* Ab = sm + SM_A + (ck % 3) * ABUF;
#pragma unroll
                        for (int ktl = 0; ktl < 5; ++ktl) {
                            const int kk = ck * 5 + ktl;
                            uint2 a[2][2];
#pragma unroll
                            for (int q = 0; q < 2; ++q) {
                                const char* base = Ab + ((mw * 2 + q) * 16 + g) * ASTRIDE
                                                   + ktl * 32 + tid4 * 8;
                                a[q][0] = *(const uint2*)base;
                                a[q][1] = *(const uint2*)(base + 8 * ASTRIDE);
                            }
#pragma unroll
                            for (int si = 0; si < 3; ++si) {
                                int sl = slot0 + si;
                                if (sl >= nbig) sl = nbig - 1;   // clamp (results discarded)
                                uint2 w = *(const uint2*)(sm + sl * 19200 + kk * 256 + lane * 8);
#pragma unroll
                                for (int q = 0; q < 2; ++q)
                                    mma_16816(acc[si][q], a[q][0].x, a[q][1].x,
                                              a[q][0].y, a[q][1].y, w.x, w.y);
                            }
                        }
                    }
                    __syncthreads();
                }
            }

            // ---- epilogue ----
            if (cls == 1) {
                // write raw gi1 preacts to global [par][gr][b]
                const int s = r - 1;
                float* gw = g_gi1[s & 1];
#pragma unroll
                for (int si = 0; si < 3; ++si) {
                    if (si < nmy) {
                        int t = (cta - 50) * 10 + slot0 + si;
                        int gr = t * 8 + tid4 * 2;
#pragma unroll
                        for (int q = 0; q < 2; ++q) {
                            int b0 = (mw * 2 + q) * 16 + g;
                            __stcg(gw + (size_t)gr * BT + b0, acc[si][q][0]);
                            __stcg(gw + (size_t)(gr + 1) * BT + b0, acc[si][q][1]);
                            __stcg(gw + (size_t)gr * BT + b0 + 8, acc[si][q][2]);
                            __stcg(gw + (size_t)(gr + 1) * BT + b0 + 8, acc[si][q][3]);
                        }
                    }
                }
            } else {
                // write preacts to smem
#pragma unroll
                for (int si = 0; si < 3; ++si) {
                    bool valid = (cls == 0) ? (nw == 3 || nw < 3) && (nw == 3 ? si < 3 : si < 3)
                                            : (si < nmy);
                    int ps;
                    if (cls == 0) ps = (nw == 3) ? 9 + si : slot0 + si;
                    else ps = slot0 + si;
                    if (cls == 0 && nw == 2 && false) {}
                    if (valid) {
#pragma unroll
                        for (int q = 0; q < 2; ++q) {
                            int b0 = (mw * 2 + q) * 16 + g;
                            float* p0 = pre + ((ps * 64 + b0) * 8 + tid4 * 2);
                            p0[0] = acc[si][q][0]; p0[1] = acc[si][q][1];
                            float* p1 = pre + ((ps * 64 + b0 + 8) * 8 + tid4 * 2);
                            p1[0] = acc[si][q][2]; p1[1] = acc[si][q][3];
                        }
                    }
                }
                __syncthreads();

                if (cls == 0) {
#pragma unroll
                    for (int q = 0; q < 6; ++q) {
                        int pi = q * 256 + tid;
                        int b = pi & 63, j = pi >> 6;
                        int sub = j >> 3, cl = j & 7;
                        float pR  = pre[((sub) * 64 + b) * 8 + cl];
                        float pZ  = pre[((3 + sub) * 64 + b) * 8 + cl];
                        float pHN = pre[((6 + sub) * 64 + b) * 8 + cl];
                        float pIN = pre[((9 + sub) * 64 + b) * 8 + cl];
                        float vr = sigf(pR + bias[q][0]);
                        float vz = sigf(pZ + bias[q][1]);
                        float vn = tanhf_fast(pIN + bias[q][2] + vr * (pHN + bias[q][3]));
                        float h = vn + vz * (hprev[q] - vn);
                        hprev[q] = h;
                        sth16(&g_h0h[r & 1][(size_t)b * HIDN + jbase + j], h);
                        if (r == TS - 1) out[(size_t)b * HIDN + jbase + j] = h;
                    }
                } else {
                    const int s = r - 2;
                    const float* gi = g_gi1[s & 1];
#pragma unroll
                    for (int q = 0; q < 6; ++q) {
                        int pi = q * 256 + tid;
                        int b = pi & 63, j = pi >> 6;
                        int sub = j >> 3, cl = j & 7;
                        int jg = jbase + j;
                        float giR = __ldcg(gi + (size_t)jg * BT + b);
                        float giZ = __ldcg(gi + (size_t)(1200 + jg) * BT + b);
                        float giN = __ldcg(gi + (size_t)(2400 + jg) * BT + b);
                        float pR  = pre[((sub) * 64 + b) * 8 + cl];
                        float pZ  = pre[((3 + sub) * 64 + b) * 8 + cl];
                        float pHN = pre[((6 + sub) * 64 + b) * 8 + cl];
                        float vr = sigf(giR + pR + bias[q][0]);
                        float vz = sigf(giZ + pZ + bias[q][1]);
                        float vn = tanhf_fast(giN + bias[q][2] + vr * (pHN + bias[q][3]));
                        float h = vn + vz * (hprev[q] - vn);
                        hprev[q] = h;
                        sth16(&g_h1h[s & 1][(size_t)b * HIDN + jbase + j], h);
                        if (s == TS - 1) out[76800 + (size_t)b * HIDN + jbase + j] = h;
                    }
                }
            }
        }

        // ---- grid barrier ----
        __threadfence();
        __syncthreads();
        if (tid == 0) {
            unsigned a = atomicAdd(&g_arr, 1u);
            if (a == NCTA - 1) {
                g_arr = 0u;
                __threadfence();
                atomicExch(&g_epoch, (unsigned)(r + 1));
            } else {
                unsigned e;
                while (true) {
                    asm volatile("ld.global.cg.u32 %0,[%1];" : "=r"(e) : "l"(&g_epoch));
                    if (e >= (unsigned)(r + 1)) break;
                    __nanosleep(32);
                }
            }
        }
        __syncthreads();
    }
}

// ---------------- launch ----------------
extern "C" void kernel_launch(void* const* d_in, const int* in_sizes, int n_in,
                              void* d_out, int out_size) {
    const float* x     = (const float*)d_in[0];
    const float* W_ih0 = (const float*)d_in[1];
    const float* W_hh0 = (const float*)d_in[2];
    const float* b_ih0 = (const float*)d_in[3];
    const float* b_hh0 = (const float*)d_in[4];
    const float* W_ih1 = (const float*)d_in[5];
    const float* W_hh1 = (const float*)d_in[6];
    const float* b_ih1 = (const float*)d_in[7];
    const float* b_hh1 = (const float*)d_in[8];
    float* out = (float*)d_out;

    cudaFuncSetAttribute(gru_main,
                         cudaFuncAttributeMaxDynamicSharedMemorySize, SMEM_TOTAL);

    zero_state_kernel<<<(BT * HIDN + 255) / 256, 256>>>();
    {
        long total = (long)NCTA * 12 * 75 * 32;
        pack_res_kernel<<<(int)((total + 255) / 256), 256>>>(W_hh0, W_ih1, W_hh1);
    }
    pack_x_kernel<<<(50 * 9 * 2 * 32 + 255) / 256, 256>>>(W_ih0);
    conv_x_kernel<<<(TS * BT * 32 + 255) / 256, 256>>>(x);

    gru_main<<<NCTA, NTH, SMEM_TOTAL>>>(b_ih0, b_hh0, b_ih1, b_hh1, out);
}

// round 5
// speedup vs baseline: 2.0649x; 1.2041x over previous
#include <cuda_runtime.h>
#include <cuda_fp16.h>
#include <cstdint>

#define NCTA   145
#define NTH    256
#define HIDN   1200
#define BT     64
#define TS     512
#define ROUNDS 514
#define SM_XW  172800          // L0 x-weight region (after 9 slots)
#define SMEM_TOTAL 223488

// ---------------- static device scratch ----------------
__device__ uint2 g_Wpk[(size_t)NCTA * 12 * 75 * 32];   // resident-weight pack
__device__ uint2 g_Wxp[50 * 9 * 2 * 32];               // L0 x-weights pack
__device__ __align__(16) __half g_x16[TS * BT * 32];   // [t][b][32]
__device__ __align__(16) __half g_h0h[2][BT * HIDN];
__device__ __align__(16) __half g_h1h[2][BT * HIDN];
__device__ float g_gi1[2][3600 * BT];                  // [par][gate-row][b]
__device__ unsigned g_arr;
__device__ unsigned g_epoch;

// ---------------- prep kernels ----------------
__global__ void zero_state_kernel() {
    int idx = blockIdx.x * blockDim.x + threadIdx.x;
    if (idx < BT * HIDN) {
        __half z = __float2half(0.f);
        g_h0h[0][idx] = z; g_h0h[1][idx] = z;
        g_h1h[0][idx] = z; g_h1h[1][idx] = z;
    }
    if (idx == 0) { g_arr = 0u; g_epoch = 0u; }
}

__global__ void pack_res_kernel(const float* __restrict__ Whh0,
                                const float* __restrict__ Wih1,
                                const float* __restrict__ Whh1) {
    long idx = (long)blockIdx.x * blockDim.x + threadIdx.x;
    const long total = (long)NCTA * 12 * 75 * 32;
    if (idx >= total) return;
    int lane = (int)(idx & 31);
    long u = idx >> 5;
    int kt = (int)(u % 75);
    long v = u / 75;
    int s = (int)(v % 12);
    int cta = (int)(v / 12);
    const float* W;
    int row0;
    if (cta < 50) {
        if (s >= 9) return;
        W = Whh0; row0 = (s / 3) * 1200 + cta * 24 + (s % 3) * 8;
    } else if (cta < 95) {
        if (s >= 10) return;
        W = Wih1; row0 = ((cta - 50) * 10 + s) * 8;
    } else {
        if (s >= 9) return;
        W = Whh1; row0 = (s / 3) * 1200 + (cta - 95) * 24 + (s % 3) * 8;
    }
    int row = row0 + (lane >> 2);
    int k0 = kt * 16 + (lane & 3) * 4;
    const float* src = W + (size_t)row * HIDN + k0;
    unsigned h[4];
#pragma unroll
    for (int c = 0; c < 4; ++c)
        h[c] = (unsigned)__half_as_ushort(__float2half_rn(src[c]));
    uint2 o; o.x = h[0] | (h[1] << 16); o.y = h[2] | (h[3] << 16);
    g_Wpk[idx] = o;
}

__global__ void pack_x_kernel(const float* __restrict__ Wih0) {
    int idx = blockIdx.x * blockDim.x + threadIdx.x;
    if (idx >= 50 * 9 * 2 * 32) return;
    int lane = idx & 31;
    int kt = (idx >> 5) & 1;
    int u = idx >> 6;
    int s = u % 9;
    int cta = u / 9;
    int row = (s / 3) * 1200 + cta * 24 + (s % 3) * 8 + (lane >> 2);
    int k0 = kt * 16 + (lane & 3) * 4;
    unsigned h[4];
#pragma unroll
    for (int c = 0; c < 4; ++c) {
        int k = k0 + c;
        float v = (k < 30) ? Wih0[(size_t)row * 30 + k] : 0.f;
        h[c] = (unsigned)__half_as_ushort(__float2half_rn(v));
    }
    uint2 o; o.x = h[0] | (h[1] << 16); o.y = h[2] | (h[3] << 16);
    g_Wxp[idx] = o;
}

__global__ void conv_x_kernel(const float* __restrict__ x) {
    int idx = blockIdx.x * blockDim.x + threadIdx.x;
    if (idx >= TS * BT * 32) return;
    int i = idx & 31;
    int b = (idx >> 5) & 63;
    int t = idx >> 11;
    float v = (i < 30) ? x[((size_t)b * TS + t) * 30 + i] : 0.f;
    g_x16[idx] = __float2half_rn(v);
}

// ---------------- device helpers ----------------
__device__ __forceinline__ void mma_16816(float c[4],
    unsigned a0, unsigned a1, unsigned a2, unsigned a3, unsigned b0, unsigned b1) {
    asm volatile(
        "mma.sync.aligned.m16n8k16.row.col.f32.f16.f16.f32 "
        "{%0,%1,%2,%3},{%4,%5,%6,%7},{%8,%9},{%0,%1,%2,%3};"
        : "+f"(c[0]), "+f"(c[1]), "+f"(c[2]), "+f"(c[3])
        : "r"(a0), "r"(a1), "r"(a2), "r"(a3), "r"(b0), "r"(b1));
}
__device__ __forceinline__ void cpa16(void* s, const void* g) {
    unsigned sa = (unsigned)__cvta_generic_to_shared(s);
    asm volatile("cp.async.cg.shared.global [%0],[%1],16;" :: "r"(sa), "l"(g));
}
__device__ __forceinline__ void cp_commit() { asm volatile("cp.async.commit_group;"); }
template <int N> __device__ __forceinline__ void cp_wait() {
    asm volatile("cp.async.wait_group %0;" :: "n"(N));
}
__device__ __forceinline__ float sigf(float x) {
    return __fdividef(1.f, 1.f + __expf(-x));
}
__device__ __forceinline__ float tanhf_fast(float x) {
    return __fdividef(2.f, 1.f + __expf(-2.f * x)) - 1.f;
}
__device__ __forceinline__ void sth16(__half* p, float v) {
    unsigned short u = __half_as_ushort(__float2half_rn(v));
    asm volatile("st.global.cg.u16 [%0], %1;" :: "l"(p), "h"(u) : "memory");
}

// A fragment load: rows rowA0+mt*16+{0,8}, 8 bytes per lane at kt*32+tid4*8
__device__ __forceinline__ void ldA(uint2 (&dst)[2][2], const char* aBase,
                                    int rowA0, int tid4, int kt) {
#pragma unroll
    for (int mt = 0; mt < 2; ++mt)
#pragma unroll
        for (int p = 0; p < 2; ++p) {
            const char* ptr = aBase + (size_t)(rowA0 + mt * 16 + p * 8) * 2400
                              + kt * 32 + tid4 * 8;
            asm volatile("ld.global.cg.v2.u32 {%0,%1},[%2];"
                         : "=r"(dst[mt][p].x), "=r"(dst[mt][p].y) : "l"(ptr));
        }
}

template<int NS>
__device__ __forceinline__ void do_slots(const char* smB, int kt, int lane,
                                         const uint2 (&cur)[2][2], float (&acc)[2][NS][4]) {
#pragma unroll
    for (int s = 0; s < NS; ++s) {
        uint2 w = *(const uint2*)(smB + s * 19200 + kt * 256 + lane * 8);
#pragma unroll
        for (int mt = 0; mt < 2; ++mt)
            mma_16816(acc[mt][s], cur[mt][0].x, cur[mt][1].x,
                      cur[mt][0].y, cur[mt][1].y, w.x, w.y);
    }
}

template<int NS>
__device__ __forceinline__ void run_kloop(const char* aBase, const char* smB,
        int kt_lo, int kt_hi, int rowA0, int tid4, int lane, float (&acc)[2][NS][4]) {
    uint2 b0[2][2], b1[2][2];
    ldA(b0, aBase, rowA0, tid4, kt_lo);
    ldA(b1, aBase, rowA0, tid4, kt_lo + 1);
#pragma unroll 1
    for (int kt = kt_lo; kt < kt_hi; kt += 2) {
        {
            uint2 cur[2][2];
#pragma unroll
            for (int mt = 0; mt < 2; ++mt) { cur[mt][0] = b0[mt][0]; cur[mt][1] = b0[mt][1]; }
            if (kt + 2 < kt_hi) ldA(b0, aBase, rowA0, tid4, kt + 2);
            do_slots<NS>(smB, kt, lane, cur, acc);
        }
        if (kt + 1 < kt_hi) {
            uint2 cur[2][2];
#pragma unroll
            for (int mt = 0; mt < 2; ++mt) { cur[mt][0] = b1[mt][0]; cur[mt][1] = b1[mt][1]; }
            if (kt + 3 < kt_hi) ldA(b1, aBase, rowA0, tid4, kt + 3);
            do_slots<NS>(smB, kt + 1, lane, cur, acc);
        }
    }
}

// ---------------- persistent kernel ----------------
__global__ void __launch_bounds__(NTH, 1) gru_main(
    const float* __restrict__ b_ih0, const float* __restrict__ b_hh0,
    const float* __restrict__ b_ih1, const float* __restrict__ b_hh1,
    float* __restrict__ out)
{
    extern __shared__ char sm[];
    const int cta  = blockIdx.x;
    const int tid  = threadIdx.x;
    const int wid  = tid >> 5;
    const int lane = tid & 31;
    const int mw   = wid >> 2;        // 0..1
    const int kw   = wid & 3;         // 0..3 k-split group
    const int g    = lane >> 2;
    const int tid4 = lane & 3;
    const int cls  = (cta < 50) ? 0 : (cta < 95) ? 1 : 2;
    const int nbig = (cls == 1) ? 10 : 9;

    const int kt_lo = kw * 19;
    const int kt_hi = (kw == 3) ? 75 : kt_lo + 19;
    const int rowA0 = mw * 32 + g;

    const int PB_off  = (cls == 0) ? 177408 : (cls == 1) ? 192000 : 172800;
    __half* PBh = (__half*)(sm + PB_off);
    float*  pre = (float*)(sm + PB_off + ((cls == 1) ? 30720 : 27648));

    // ---- load resident weights (once) ----
    {
        const uint2* wsrc = g_Wpk + (size_t)cta * 12 * 75 * 32;
        int n16 = nbig * 1200;
        for (int i = tid; i < n16; i += NTH)
            cpa16(sm + i * 16, wsrc + i * 2);
        if (cls == 0) {
            const uint2* xs = g_Wxp + cta * 576;
            for (int i = tid; i < 288; i += NTH)
                cpa16(sm + SM_XW + i * 16, xs + i * 2);
        }
        cp_commit();
        cp_wait<0>();
        __syncthreads();
    }

    // ---- combine-side setup ----
    const int jbase = (cls == 0) ? cta * 24 : (cls == 2) ? (cta - 95) * 24 : 0;
    float bias[6][4];
    float hprev[6];
    if (cls != 1) {
        const float* bi = (cls == 0) ? b_ih0 : b_ih1;
        const float* bh = (cls == 0) ? b_hh0 : b_hh1;
#pragma unroll
        for (int q = 0; q < 6; ++q) {
            int jg = jbase + ((q * 256 + tid) >> 6);
            bias[q][0] = __ldg(bi + jg) + __ldg(bh + jg);
            bias[q][1] = __ldg(bi + 1200 + jg) + __ldg(bh + 1200 + jg);
            bias[q][2] = __ldg(bi + 2400 + jg);
            bias[q][3] = __ldg(bh + 2400 + jg);
            hprev[q] = 0.f;
        }
    }

    for (int r = 0; r < ROUNDS; ++r) {
        const bool act = (cls == 0) ? (r < TS)
                        : (cls == 1) ? (r >= 1 && r <= TS)
                                     : (r >= 2);
        if (act) {
            if (cls == 1) {
                // ---------------- I1: gi1 = out0 @ W_ih1^T ----------------
                float acc[2][10][4];
#pragma unroll
                for (int mt = 0; mt < 2; ++mt)
#pragma unroll
                    for (int s = 0; s < 10; ++s)
#pragma unroll
                        for (int c = 0; c < 4; ++c) acc[mt][s][c] = 0.f;

                const char* aBase = (const char*)g_h0h[(r + 1) & 1];
                run_kloop<10>(aBase, sm, kt_lo, kt_hi, rowA0, tid4, lane, acc);

                if (kw > 0) {
#pragma unroll
                    for (int mt = 0; mt < 2; ++mt)
#pragma unroll
                        for (int s = 0; s < 10; ++s)
#pragma unroll
                            for (int p = 0; p < 2; ++p) {
                                int b = rowA0 + mt * 16 + p * 8;
                                __half2 v = __floats2half2_rn(acc[mt][s][p * 2], acc[mt][s][p * 2 + 1]);
                                *(__half2*)(PBh + ((kw - 1) * 10 + s) * 512 + b * 8 + tid4 * 2) = v;
                            }
                }
                __syncthreads();
                if (kw == 0) {
                    float* gw = g_gi1[(r - 1) & 1];
#pragma unroll
                    for (int mt = 0; mt < 2; ++mt)
#pragma unroll
                        for (int s = 0; s < 10; ++s)
#pragma unroll
                            for (int p = 0; p < 2; ++p) {
                                int b = rowA0 + mt * 16 + p * 8;
#pragma unroll
                                for (int grp = 0; grp < 3; ++grp) {
                                    __half2 u = *(__half2*)(PBh + (grp * 10 + s) * 512 + b * 8 + tid4 * 2);
                                    acc[mt][s][p * 2]     += __low2float(u);
                                    acc[mt][s][p * 2 + 1] += __high2float(u);
                                }
                                int gr = ((cta - 50) * 10 + s) * 8 + tid4 * 2;
                                __stcg(gw + (size_t)gr * BT + b, acc[mt][s][p * 2]);
                                __stcg(gw + (size_t)(gr + 1) * BT + b, acc[mt][s][p * 2 + 1]);
                            }
                }
            } else {
                // ---------------- L0 / H1 ----------------
                float acc[2][9][4];
#pragma unroll
                for (int mt = 0; mt < 2; ++mt)
#pragma unroll
                    for (int s = 0; s < 9; ++s)
#pragma unroll
                        for (int c = 0; c < 4; ++c) acc[mt][s][c] = 0.f;
                float accIN[2][3][4];

                const char* aBase = (cls == 2) ? (const char*)g_h1h[(r + 1) & 1]
                                               : (const char*)g_h0h[(r + 1) & 1];

                if (cls == 0 && kw == 0) {
#pragma unroll
                    for (int mt = 0; mt < 2; ++mt)
#pragma unroll
                        for (int s = 0; s < 3; ++s)
#pragma unroll
                            for (int c = 0; c < 4; ++c) accIN[mt][s][c] = 0.f;
                    // x-GEMM (K=32)
                    const uint2* pA = (const uint2*)(g_x16 + (size_t)r * BT * 32);
#pragma unroll
                    for (int kt2 = 0; kt2 < 2; ++kt2) {
                        uint2 a[2][2];
#pragma unroll
                        for (int mt = 0; mt < 2; ++mt) {
                            int row = rowA0 + mt * 16;
                            a[mt][0] = __ldg(&pA[row * 8 + kt2 * 4 + tid4]);
                            a[mt][1] = __ldg(&pA[(row + 8) * 8 + kt2 * 4 + tid4]);
                        }
#pragma unroll
                        for (int s = 0; s < 9; ++s) {
                            uint2 w = *(const uint2*)(sm + SM_XW + ((s * 2 + kt2) * 32 + lane) * 8);
#pragma unroll
                            for (int mt = 0; mt < 2; ++mt) {
                                float* tgt = (s < 6) ? acc[mt][s] : accIN[mt][s - 6];
                                mma_16816(tgt, a[mt][0].x, a[mt][1].x,
                                          a[mt][0].y, a[mt][1].y, w.x, w.y);
                            }
                        }
                    }
                }

                run_kloop<9>(aBase, sm, kt_lo, kt_hi, rowA0, tid4, lane, acc);

                if (kw > 0) {
#pragma unroll
                    for (int mt = 0; mt < 2; ++mt)
#pragma unroll
                        for (int s = 0; s < 9; ++s)
#pragma unroll
                            for (int p = 0; p < 2; ++p) {
                                int b = rowA0 + mt * 16 + p * 8;
                                __half2 v = __floats2half2_rn(acc[mt][s][p * 2], acc[mt][s][p * 2 + 1]);
                                *(__half2*)(PBh + ((kw - 1) * 9 + s) * 512 + b * 8 + tid4 * 2) = v;
                            }
                }
                __syncthreads();
                if (kw == 0) {
#pragma unroll
                    for (int mt = 0; mt < 2; ++mt)
#pragma unroll
                        for (int s = 0; s < 9; ++s)
#pragma unroll
                            for (int p = 0; p < 2; ++p) {
                                int b = rowA0 + mt * 16 + p * 8;
#pragma unroll
                                for (int grp = 0; grp < 3; ++grp) {
                                    __half2 u = *(__half2*)(PBh + (grp * 9 + s) * 512 + b * 8 + tid4 * 2);
                                    acc[mt][s][p * 2]     += __low2float(u);
                                    acc[mt][s][p * 2 + 1] += __high2float(u);
                                }
                                *(float2*)(pre + (s * 64 + b) * 8 + tid4 * 2) =
                                    make_float2(acc[mt][s][p * 2], acc[mt][s][p * 2 + 1]);
                            }
                    if (cls == 0) {
                        // write i_n into PB (fp16), rows owned by this warp
#pragma unroll
                        for (int mt = 0; mt < 2; ++mt)
#pragma unroll
                            for (int s = 0; s < 3; ++s)
#pragma unroll
                                for (int p = 0; p < 2; ++p) {
                                    int b = rowA0 + mt * 16 + p * 8;
                                    __half2 v = __floats2half2_rn(accIN[mt][s][p * 2], accIN[mt][s][p * 2 + 1]);
                                    *(__half2*)(PBh + s * 512 + b * 8 + tid4 * 2) = v;
                                }
                    }
                }
                __syncthreads();

                // ---- combine (all 256 threads) ----
                if (cls == 0) {
#pragma unroll
                    for (int q = 0; q < 6; ++q) {
                        int pi = q * 256 + tid;
                        int b = pi & 63, j = pi >> 6;
                        int sub = j >> 3, cl = j & 7;
                        float pR  = pre[(sub * 64 + b) * 8 + cl];
                        float pZ  = pre[((3 + sub) * 64 + b) * 8 + cl];
                        float pHN = pre[((6 + sub) * 64 + b) * 8 + cl];
                        float pIN = __half2float(PBh[(sub * 64 + b) * 8 + cl]);
                        float vr = sigf(pR + bias[q][0]);
                        float vz = sigf(pZ + bias[q][1]);
                        float vn = tanhf_fast(pIN + bias[q][2] + vr * (pHN + bias[q][3]));
                        float h = vn + vz * (hprev[q] - vn);
                        hprev[q] = h;
                        sth16(&g_h0h[r & 1][(size_t)b * HIDN + jbase + j], h);
                        if (r == TS - 1) out[(size_t)b * HIDN + jbase + j] = h;
                    }
                } else {
                    const int s = r - 2;
                    const float* gi = g_gi1[s & 1];
#pragma unroll
                    for (int q = 0; q < 6; ++q) {
                        int pi = q * 256 + tid;
                        int b = pi & 63, j = pi >> 6;
                        int sub = j >> 3, cl = j & 7;
                        int jg = jbase + j;
                        float giR = __ldcg(gi + (size_t)jg * BT + b);
                        float giZ = __ldcg(gi + (size_t)(1200 + jg) * BT + b);
                        float giN = __ldcg(gi + (size_t)(2400 + jg) * BT + b);
                        float pR  = pre[(sub * 64 + b) * 8 + cl];
                        float pZ  = pre[((3 + sub) * 64 + b) * 8 + cl];
                        float pHN = pre[((6 + sub) * 64 + b) * 8 + cl];
                        float vr = sigf(giR + pR + bias[q][0]);
                        float vz = sigf(giZ + pZ + bias[q][1]);
                        float vn = tanhf_fast(giN + bias[q][2] + vr * (pHN + bias[q][3]));
                        float h = vn + vz * (hprev[q] - vn);
                        hprev[q] = h;
                        sth16(&g_h1h[s & 1][(size_t)b * HIDN + jbase + j], h);
                        if (s == TS - 1) out[76800 + (size_t)b * HIDN + jbase + j] = h;
                    }
                }
            }
        }

        // ---- grid barrier ----
        __threadfence();
        __syncthreads();
        if (tid == 0) {
            unsigned a = atomicAdd(&g_arr, 1u);
            if (a == NCTA - 1) {
                g_arr = 0u;
                __threadfence();
                atomicExch(&g_epoch, (unsigned)(r + 1));
            }
        }
        unsigned e;
        while (true) {
            asm volatile("ld.global.acquire.gpu.u32 %0,[%1];" : "=r"(e) : "l"(&g_epoch));
            if (e >= (unsigned)(r + 1)) break;
            __nanosleep(20);
        }
    }
}

// ---------------- launch ----------------
extern "C" void kernel_launch(void* const* d_in, const int* in_sizes, int n_in,
                              void* d_out, int out_size) {
    const float* x     = (const float*)d_in[0];
    const float* W_ih0 = (const float*)d_in[1];
    const float* W_hh0 = (const float*)d_in[2];
    const float* b_ih0 = (const float*)d_in[3];
    const float* b_hh0 = (const float*)d_in[4];
    const float* W_ih1 = (const float*)d_in[5];
    const float* W_hh1 = (const float*)d_in[6];
    const float* b_ih1 = (const float*)d_in[7];
    const float* b_hh1 = (const float*)d_in[8];
    float* out = (float*)d_out;

    cudaFuncSetAttribute(gru_main,
                         cudaFuncAttributeMaxDynamicSharedMemorySize, SMEM_TOTAL);

    zero_state_kernel<<<(BT * HIDN + 255) / 256, 256>>>();
    {
        long total = (long)NCTA * 12 * 75 * 32;
        pack_res_kernel<<<(int)((total + 255) / 256), 256>>>(W_hh0, W_ih1, W_hh1);
    }
    pack_x_kernel<<<(50 * 9 * 2 * 32 + 255) / 256, 256>>>(W_ih0);
    conv_x_kernel<<<(TS * BT * 32 + 255) / 256, 256>>>(x);

    gru_main<<<NCTA, NTH, SMEM_TOTAL>>>(b_ih0, b_hh0, b_ih1, b_hh1, out);
}

// round 7
// speedup vs baseline: 2.2873x; 1.1077x over previous
#include <cuda_runtime.h>
#include <cuda_fp16.h>
#include <cstdint>

#define NCTA   145
#define NTH    256
#define HIDN   1200
#define BT     64
#define TS     512
#define ROUNDS 514
#define SM_XW  172800
#define SMEM_TOTAL 222720

// ---------------- static device scratch ----------------
__device__ uint2 g_Wpk[(size_t)NCTA * 12 * 75 * 32];
__device__ uint2 g_Wxp[50 * 9 * 2 * 32];
__device__ __align__(16) __half g_x16[TS * BT * 32];
__device__ __align__(16) __half g_h0h[2][BT * HIDN];
__device__ __align__(16) __half g_h1h[2][BT * HIDN];
__device__ float g_gi1[2][3600 * BT];
__device__ unsigned g_arr;
__device__ unsigned g_epoch;

// ---------------- prep kernels ----------------
__global__ void zero_state_kernel() {
    int idx = blockIdx.x * blockDim.x + threadIdx.x;
    if (idx < BT * HIDN) {
        __half z = __float2half(0.f);
        g_h0h[0][idx] = z; g_h0h[1][idx] = z;
        g_h1h[0][idx] = z; g_h1h[1][idx] = z;
    }
    if (idx == 0) { g_arr = 0u; g_epoch = 0u; }
}

__global__ void pack_res_kernel(const float* __restrict__ Whh0,
                                const float* __restrict__ Wih1,
                                const float* __restrict__ Whh1) {
    long idx = (long)blockIdx.x * blockDim.x + threadIdx.x;
    const long total = (long)NCTA * 12 * 75 * 32;
    if (idx >= total) return;
    int lane = (int)(idx & 31);
    long u = idx >> 5;
    int kt = (int)(u % 75);
    long v = u / 75;
    int s = (int)(v % 12);
    int cta = (int)(v / 12);
    const float* W;
    int row0;
    if (cta < 50) {
        if (s >= 9) return;
        W = Whh0; row0 = (s / 3) * 1200 + cta * 24 + (s % 3) * 8;
    } else if (cta < 95) {
        if (s >= 10) return;
        W = Wih1; row0 = ((cta - 50) * 10 + s) * 8;
    } else {
        if (s >= 9) return;
        W = Whh1; row0 = (s / 3) * 1200 + (cta - 95) * 24 + (s % 3) * 8;
    }
    int row = row0 + (lane >> 2);
    int k0 = kt * 16 + (lane & 3) * 4;
    const float* src = W + (size_t)row * HIDN + k0;
    unsigned h[4];
#pragma unroll
    for (int c = 0; c < 4; ++c)
        h[c] = (unsigned)__half_as_ushort(__float2half_rn(src[c]));
    uint2 o; o.x = h[0] | (h[1] << 16); o.y = h[2] | (h[3] << 16);
    g_Wpk[idx] = o;
}

__global__ void pack_x_kernel(const float* __restrict__ Wih0) {
    int idx = blockIdx.x * blockDim.x + threadIdx.x;
    if (idx >= 50 * 9 * 2 * 32) return;
    int lane = idx & 31;
    int kt = (idx >> 5) & 1;
    int u = idx >> 6;
    int s = u % 9;
    int cta = u / 9;
    int row = (s / 3) * 1200 + cta * 24 + (s % 3) * 8 + (lane >> 2);
    int k0 = kt * 16 + (lane & 3) * 4;
    unsigned h[4];
#pragma unroll
    for (int c = 0; c < 4; ++c) {
        int k = k0 + c;
        float v = (k < 30) ? Wih0[(size_t)row * 30 + k] : 0.f;
        h[c] = (unsigned)__half_as_ushort(__float2half_rn(v));
    }
    uint2 o; o.x = h[0] | (h[1] << 16); o.y = h[2] | (h[3] << 16);
    g_Wxp[idx] = o;
}

__global__ void conv_x_kernel(const float* __restrict__ x) {
    int idx = blockIdx.x * blockDim.x + threadIdx.x;
    if (idx >= TS * BT * 32) return;
    int i = idx & 31;
    int b = (idx >> 5) & 63;
    int t = idx >> 11;
    float v = (i < 30) ? x[((size_t)b * TS + t) * 30 + i] : 0.f;
    g_x16[idx] = __float2half_rn(v);
}

// ---------------- device helpers ----------------
__device__ __forceinline__ void mma_16816(float c[4],
    unsigned a0, unsigned a1, unsigned a2, unsigned a3, unsigned b0, unsigned b1) {
    asm volatile(
        "mma.sync.aligned.m16n8k16.row.col.f32.f16.f16.f32 "
        "{%0,%1,%2,%3},{%4,%5,%6,%7},{%8,%9},{%0,%1,%2,%3};"
        : "+f"(c[0]), "+f"(c[1]), "+f"(c[2]), "+f"(c[3])
        : "r"(a0), "r"(a1), "r"(a2), "r"(a3), "r"(b0), "r"(b1));
}
__device__ __forceinline__ void cpa16(void* s, const void* g) {
    unsigned sa = (unsigned)__cvta_generic_to_shared(s);
    asm volatile("cp.async.cg.shared.global [%0],[%1],16;" :: "r"(sa), "l"(g));
}
__device__ __forceinline__ void cp_commit() { asm volatile("cp.async.commit_group;"); }
template <int N> __device__ __forceinline__ void cp_wait() {
    asm volatile("cp.async.wait_group %0;" :: "n"(N));
}
__device__ __forceinline__ float sigf(float x) {
    return __fdividef(1.f, 1.f + __expf(-x));
}
__device__ __forceinline__ float tanhf_fast(float x) {
    return __fdividef(2.f, 1.f + __expf(-2.f * x)) - 1.f;
}

__device__ __forceinline__ void ldA(uint2 (&dst)[2][2], const char* aBase,
                                    int rowA0, int tid4, int kt) {
#pragma unroll
    for (int mt = 0; mt < 2; ++mt)
#pragma unroll
        for (int p = 0; p < 2; ++p) {
            const char* ptr = aBase + (size_t)(rowA0 + mt * 16 + p * 8) * 2400
                              + kt * 32 + tid4 * 8;
            asm volatile("ld.global.cg.v2.u32 {%0,%1},[%2];"
                         : "=r"(dst[mt][p].x), "=r"(dst[mt][p].y) : "l"(ptr));
        }
}

template<int NS>
__device__ __forceinline__ void do_slots(const char* smB, int kt, int lane,
                                         const uint2 (&cur)[2][2], float (&acc)[2][NS][4]) {
#pragma unroll
    for (int s = 0; s < NS; ++s) {
        uint2 w = *(const uint2*)(smB + s * 19200 + kt * 256 + lane * 8);
#pragma unroll
        for (int mt = 0; mt < 2; ++mt)
            mma_16816(acc[mt][s], cur[mt][0].x, cur[mt][1].x,
                      cur[mt][0].y, cur[mt][1].y, w.x, w.y);
    }
}

template<int NS>
__device__ __forceinline__ void run_kloop(const char* aBase, const char* smB,
        int kt_lo, int kt_hi, int rowA0, int tid4, int lane, float (&acc)[2][NS][4]) {
    uint2 b0[2][2], b1[2][2];
    ldA(b0, aBase, rowA0, tid4, kt_lo);
    ldA(b1, aBase, rowA0, tid4, kt_lo + 1);
#pragma unroll 1
    for (int kt = kt_lo; kt < kt_hi; kt += 2) {
        {
            uint2 cur[2][2];
#pragma unroll
            for (int mt = 0; mt < 2; ++mt) { cur[mt][0] = b0[mt][0]; cur[mt][1] = b0[mt][1]; }
            if (kt + 2 < kt_hi) ldA(b0, aBase, rowA0, tid4, kt + 2);
            do_slots<NS>(smB, kt, lane, cur, acc);
        }
        if (kt + 1 < kt_hi) {
            uint2 cur[2][2];
#pragma unroll
            for (int mt = 0; mt < 2; ++mt) { cur[mt][0] = b1[mt][0]; cur[mt][1] = b1[mt][1]; }
            if (kt + 3 < kt_hi) ldA(b1, aBase, rowA0, tid4, kt + 3);
            do_slots<NS>(smB, kt + 1, lane, cur, acc);
        }
    }
}

template<int NS>
__device__ __forceinline__ void writePB(__half* PBh, int grp, const float (&acc)[2][NS][4],
                                        int rowA0, int tid4) {
#pragma unroll
    for (int mt = 0; mt < 2; ++mt)
#pragma unroll
        for (int s = 0; s < NS; ++s)
#pragma unroll
            for (int p = 0; p < 2; ++p) {
                int b = rowA0 + mt * 16 + p * 8;
                __half2 v = __floats2half2_rn(acc[mt][s][p * 2], acc[mt][s][p * 2 + 1]);
                *(__half2*)(PBh + (grp * NS + s) * 512 + b * 8 + tid4 * 2) = v;
            }
}
template<int NS>
__device__ __forceinline__ void addPB(__half* PBh, int grp, float (&acc)[2][NS][4],
                                      int rowA0, int tid4) {
#pragma unroll
    for (int mt = 0; mt < 2; ++mt)
#pragma unroll
        for (int s = 0; s < NS; ++s)
#pragma unroll
            for (int p = 0; p < 2; ++p) {
                int b = rowA0 + mt * 16 + p * 8;
                __half2 u = *(__half2*)(PBh + (grp * NS + s) * 512 + b * 8 + tid4 * 2);
                acc[mt][s][p * 2]     += __low2float(u);
                acc[mt][s][p * 2 + 1] += __high2float(u);
            }
}

// ---------------- persistent kernel ----------------
__global__ void __launch_bounds__(NTH, 1) gru_main(
    const float* __restrict__ b_ih0, const float* __restrict__ b_hh0,
    const float* __restrict__ b_ih1, const float* __restrict__ b_hh1,
    float* __restrict__ out)
{
    extern __shared__ char sm[];
    const int cta  = blockIdx.x;
    const int tid  = threadIdx.x;
    const int wid  = tid >> 5;
    const int lane = tid & 31;
    const int mw   = wid >> 2;
    const int kw   = wid & 3;
    const int g    = lane >> 2;
    const int tid4 = lane & 3;
    const int cls  = (cta < 50) ? 0 : (cta < 95) ? 1 : 2;
    const int nbig = (cls == 1) ? 10 : 9;

    const int kt_lo = kw * 19;
    const int kt_hi = (kw == 3) ? 75 : kt_lo + 19;
    const int rowA0 = mw * 32 + g;

    const int PB_off = (cls == 0) ? 177408 : (cls == 1) ? 192000 : 172800;
    __half* PBh = (__half*)(sm + PB_off);
    const int pbsz = 2 * nbig * 512 * 2;
    __half* INb = (__half*)(sm + PB_off + pbsz);
    float*  pre = (float*)(sm + PB_off + pbsz + ((cls == 0) ? 3072 : 0));
    __half* hbuf = (__half*)((char*)pre + 9 * 64 * 9 * 4);

    // ---- load resident weights ----
    {
        const uint2* wsrc = g_Wpk + (size_t)cta * 12 * 75 * 32;
        int n16 = nbig * 1200;
        for (int i = tid; i < n16; i += NTH)
            cpa16(sm + i * 16, wsrc + i * 2);
        if (cls == 0) {
            const uint2* xs = g_Wxp + cta * 576;
            for (int i = tid; i < 288; i += NTH)
                cpa16(sm + SM_XW + i * 16, xs + i * 2);
        }
        cp_commit();
        cp_wait<0>();
        __syncthreads();
    }

    // ---- combine-side setup ----
    const int jbase = (cls == 0) ? cta * 24 : (cls == 2) ? (cta - 95) * 24 : 0;
    float bias[6][4];
    float hprev[6];
    if (cls != 1) {
        const float* bi = (cls == 0) ? b_ih0 : b_ih1;
        const float* bh = (cls == 0) ? b_hh0 : b_hh1;
#pragma unroll
        for (int q = 0; q < 6; ++q) {
            int jg = jbase + ((q * 256 + tid) >> 6);
            bias[q][0] = __ldg(bi + jg) + __ldg(bh + jg);
            bias[q][1] = __ldg(bi + 1200 + jg) + __ldg(bh + 1200 + jg);
            bias[q][2] = __ldg(bi + 2400 + jg);
            bias[q][3] = __ldg(bh + 2400 + jg);
            hprev[q] = 0.f;
        }
    }

    for (int r = 0; r < ROUNDS; ++r) {
        const bool act = (cls == 0) ? (r < TS)
                        : (cls == 1) ? (r >= 1 && r <= TS)
                                     : (r >= 2);
        if (act) {
            if (cls == 1) {
                // ---------------- I1 ----------------
                float acc[2][10][4];
#pragma unroll
                for (int mt = 0; mt < 2; ++mt)
#pragma unroll
                    for (int s = 0; s < 10; ++s)
#pragma unroll
                        for (int c = 0; c < 4; ++c) acc[mt][s][c] = 0.f;

                const char* aBase = (const char*)g_h0h[(r + 1) & 1];
                run_kloop<10>(aBase, sm, kt_lo, kt_hi, rowA0, tid4, lane, acc);

                if (kw == 1) writePB<10>(PBh, 0, acc, rowA0, tid4);
                if (kw == 3) writePB<10>(PBh, 1, acc, rowA0, tid4);
                __syncthreads();
                if (kw == 0) addPB<10>(PBh, 0, acc, rowA0, tid4);
                if (kw == 2) { addPB<10>(PBh, 1, acc, rowA0, tid4);
                               writePB<10>(PBh, 1, acc, rowA0, tid4); }
                __syncthreads();
                if (kw == 0) {
                    addPB<10>(PBh, 1, acc, rowA0, tid4);
                    float* gw = g_gi1[(r - 1) & 1];
#pragma unroll
                    for (int mt = 0; mt < 2; ++mt)
#pragma unroll
                        for (int s = 0; s < 10; ++s)
#pragma unroll
                            for (int p = 0; p < 2; ++p) {
                                int b = rowA0 + mt * 16 + p * 8;
                                int gr = ((cta - 50) * 10 + s) * 8 + tid4 * 2;
                                __stcg(gw + (size_t)gr * BT + b, acc[mt][s][p * 2]);
                                __stcg(gw + (size_t)(gr + 1) * BT + b, acc[mt][s][p * 2 + 1]);
                            }
                }
            } else {
                // ---------------- L0 / H1 ----------------
                float acc[2][9][4];
#pragma unroll
                for (int mt = 0; mt < 2; ++mt)
#pragma unroll
                    for (int s = 0; s < 9; ++s)
#pragma unroll
                        for (int c = 0; c < 4; ++c) acc[mt][s][c] = 0.f;

                const char* aBase = (cls == 2) ? (const char*)g_h1h[(r + 1) & 1]
                                               : (const char*)g_h0h[(r + 1) & 1];

                float accIN[2][3][4];
                if (cls == 0 && kw == 3) {
#pragma unroll
                    for (int mt = 0; mt < 2; ++mt)
#pragma unroll
                        for (int s = 0; s < 3; ++s)
#pragma unroll
                            for (int c = 0; c < 4; ++c) accIN[mt][s][c] = 0.f;
                    const uint2* pA = (const uint2*)(g_x16 + (size_t)r * BT * 32);
#pragma unroll
                    for (int kt2 = 0; kt2 < 2; ++kt2) {
                        uint2 a[2][2];
#pragma unroll
                        for (int mt = 0; mt < 2; ++mt) {
                            int row = rowA0 + mt * 16;
                            a[mt][0] = __ldg(&pA[row * 8 + kt2 * 4 + tid4]);
                            a[mt][1] = __ldg(&pA[(row + 8) * 8 + kt2 * 4 + tid4]);
                        }
#pragma unroll
                        for (int s = 0; s < 9; ++s) {
                            uint2 w = *(const uint2*)(sm + SM_XW + ((s * 2 + kt2) * 32 + lane) * 8);
#pragma unroll
                            for (int mt = 0; mt < 2; ++mt) {
                                float* tgt = (s < 6) ? acc[mt][s] : accIN[mt][s - 6];
                                mma_16816(tgt, a[mt][0].x, a[mt][1].x,
                                          a[mt][0].y, a[mt][1].y, w.x, w.y);
                            }
                        }
                    }
                }

                run_kloop<9>(aBase, sm, kt_lo, kt_hi, rowA0, tid4, lane, acc);

                float giPre[6][3];
                if (cls == 2) {
                    const float* gi = g_gi1[r & 1];
#pragma unroll
                    for (int q = 0; q < 6; ++q) {
                        int pi = q * 256 + tid;
                        int b = pi & 63, j = pi >> 6;
                        int jg = jbase + j;
                        giPre[q][0] = __ldcg(gi + (size_t)jg * BT + b);
                        giPre[q][1] = __ldcg(gi + (size_t)(1200 + jg) * BT + b);
                        giPre[q][2] = __ldcg(gi + (size_t)(2400 + jg) * BT + b);
                    }
                }

                if (kw == 1) writePB<9>(PBh, 0, acc, rowA0, tid4);
                if (kw == 3) {
                    writePB<9>(PBh, 1, acc, rowA0, tid4);
                    if (cls == 0) {
#pragma unroll
                        for (int mt = 0; mt < 2; ++mt)
#pragma unroll
                            for (int s = 0; s < 3; ++s)
#pragma unroll
                                for (int p = 0; p < 2; ++p) {
                                    int b = rowA0 + mt * 16 + p * 8;
                                    __half2 v = __floats2half2_rn(accIN[mt][s][p * 2],
                                                                  accIN[mt][s][p * 2 + 1]);
                                    *(__half2*)(INb + s * 512 + b * 8 + tid4 * 2) = v;
                                }
                    }
                }
                __syncthreads();
                if (kw == 0) addPB<9>(PBh, 0, acc, rowA0, tid4);
                if (kw == 2) { addPB<9>(PBh, 1, acc, rowA0, tid4);
                               writePB<9>(PBh, 1, acc, rowA0, tid4); }
                __syncthreads();
                if (kw == 0) {
                    addPB<9>(PBh, 1, acc, rowA0, tid4);
#pragma unroll
                    for (int mt = 0; mt < 2; ++mt)
#pragma unroll
                        for (int s = 0; s < 9; ++s)
#pragma unroll
                            for (int p = 0; p < 2; ++p) {
                                int b = rowA0 + mt * 16 + p * 8;
                                float* pp = pre + (s * 64 + b) * 9 + tid4 * 2;
                                pp[0] = acc[mt][s][p * 2];
                                pp[1] = acc[mt][s][p * 2 + 1];
                            }
                }
                __syncthreads();

                // ---- combine ----
                if (cls == 0) {
#pragma unroll
                    for (int q = 0; q < 6; ++q) {
                        int pi = q * 256 + tid;
                        int b = pi & 63, j = pi >> 6;
                        int sub = j >> 3, cl = j & 7;
                        float pR  = pre[((sub) * 64 + b) * 9 + cl];
                        float pZ  = pre[((3 + sub) * 64 + b) * 9 + cl];
                        float pHN = pre[((6 + sub) * 64 + b) * 9 + cl];
                        float pIN = __half2float(INb[(sub * 64 + b) * 8 + cl]);
                        float vr = sigf(pR + bias[q][0]);
                        float vz = sigf(pZ + bias[q][1]);
                        float vn = tanhf_fast(pIN + bias[q][2] + vr * (pHN + bias[q][3]));
                        float h = vn + vz * (hprev[q] - vn);
                        hprev[q] = h;
                        hbuf[b * 24 + j] = __float2half_rn(h);
                        if (r == TS - 1) out[(size_t)b * HIDN + jbase + j] = h;
                    }
                } else {
#pragma unroll
                    for (int q = 0; q < 6; ++q) {
                        int pi = q * 256 + tid;
                        int b = pi & 63, j = pi >> 6;
                        int sub = j >> 3, cl = j & 7;
                        float pR  = pre[((sub) * 64 + b) * 9 + cl];
                        float pZ  = pre[((3 + sub) * 64 + b) * 9 + cl];
                        float pHN = pre[((6 + sub) * 64 + b) * 9 + cl];
                        float vr = sigf(giPre[q][0] + pR + bias[q][0]);
                        float vz = sigf(giPre[q][1] + pZ + bias[q][1]);
                        float vn = tanhf_fast(giPre[q][2] + bias[q][2] + vr * (pHN + bias[q][3]));
                        float h = vn + vz * (hprev[q] - vn);
                        hprev[q] = h;
                        hbuf[b * 24 + j] = __float2half_rn(h);
                        if (r == TS + 1) out[76800 + (size_t)b * HIDN + jbase + j] = h;
                    }
                }
                __syncthreads();
                {
                    __half* dstH = (cls == 0) ? g_h0h[r & 1] : g_h1h[r & 1];
                    const unsigned* hb32 = (const unsigned*)hbuf;
#pragma unroll
                    for (int k = 0; k < 3; ++k) {
                        int idx = tid + k * 256;
                        int row = idx / 12, c = idx % 12;
                        unsigned v = hb32[row * 12 + c];
                        asm volatile("st.global.cg.u32 [%0], %1;"
                                     :: "l"(dstH + (size_t)row * HIDN + jbase + c * 2),
                                        "r"(v) : "memory");
                    }
                }
            }
        }

        // ---- grid barrier: tid0-only poll ----
        __threadfence();
        __syncthreads();
        if (tid == 0) {
            unsigned a = atomicAdd(&g_arr, 1u);
            if (a == NCTA - 1) {
                g_arr = 0u;
                __threadfence();
                atomicExch(&g_epoch, (unsigned)(r + 1));
            } else {
                unsigned e;
                int slp = 16;
                while (true) {
                    asm volatile("ld.global.cg.u32 %0,[%1];" : "=r"(e) : "l"(&g_epoch));
                    if (e >= (unsigned)(r + 1)) break;
                    __nanosleep(slp);
                    if (slp < 128) slp += slp;
                }
                __threadfence();
            }
        }
        __syncthreads();
    }
}

// ---------------- launch ----------------
extern "C" void kernel_launch(void* const* d_in, const int* in_sizes, int n_in,
                              void* d_out, int out_size) {
    const float* x     = (const float*)d_in[0];
    const float* W_ih0 = (const float*)d_in[1];
    const float* W_hh0 = (const float*)d_in[2];
    const float* b_ih0 = (const float*)d_in[3];
    const float* b_hh0 = (const float*)d_in[4];
    const float* W_ih1 = (const float*)d_in[5];
    const float* W_hh1 = (const float*)d_in[6];
    const float* b_ih1 = (const float*)d_in[7];
    const float* b_hh1 = (const float*)d_in[8];
    float* out = (float*)d_out;

    cudaFuncSetAttribute(gru_main,
                         cudaFuncAttributeMaxDynamicSharedMemorySize, SMEM_TOTAL);

    zero_state_kernel<<<(BT * HIDN + 255) / 256, 256>>>();
    {
        long total = (long)NCTA * 12 * 75 * 32;
        pack_res_kernel<<<(int)((total + 255) / 256), 256>>>(W_hh0, W_ih1, W_hh1);
    }
    pack_x_kernel<<<(50 * 9 * 2 * 32 + 255) / 256, 256>>>(W_ih0);
    conv_x_kernel<<<(TS * BT * 32 + 255) / 256, 256>>>(x);

    gru_main<<<NCTA, NTH, SMEM_TOTAL>>>(b_ih0, b_hh0, b_ih1, b_hh1, out);
}

// round 8
// speedup vs baseline: 2.9619x; 1.2949x over previous
#include <cuda_runtime.h>
#include <cuda_fp16.h>
#include <cstdint>

#define NCTA   145
#define NTH    256
#define HIDN   1200
#define HPAD   1216            // padded h row (halves), 2432 B = 19*128
#define BT     64
#define TS     512
#define ROUNDS 514
#define KTN    76              // k-tiles incl. phantom (38 kchunks)
#define SLOTB  19456           // 76*256 B per slot
#define SM_XW  175104          // 9*19456
#define SMEM_TOTAL 229120

// ---------------- static device scratch ----------------
__device__ uint2 g_Wpk[(size_t)NCTA * 12 * KTN * 32];
__device__ uint2 g_Wxp[50 * 9 * 2 * 32];
__device__ __align__(16) __half g_x16[TS * BT * 32];
__device__ __align__(16) __half g_h0h[2][BT * HPAD];
__device__ __align__(16) __half g_h1h[2][BT * HPAD];
__device__ float g_gi1[2][3600 * BT];
__device__ unsigned g_arr;
__device__ unsigned g_epoch;

// ---------------- fused prep kernel ----------------
// blocks [0,608): zero h arrays; [608,4704): conv_x; [4704,4817): pack_x;
// [4817,21347): pack_res
__global__ void prep_all(const float* __restrict__ x,
                         const float* __restrict__ Wih0,
                         const float* __restrict__ Whh0,
                         const float* __restrict__ Wih1,
                         const float* __restrict__ Whh1) {
    int bid = blockIdx.x;
    int t = threadIdx.x;
    if (bid < 608) {
        int idx = bid * 256 + t;                 // u32 units, 2*BT*HPAD/2 = 77824 per pair
        if (idx < 77824) ((unsigned*)g_h0h)[idx] = 0u;
        else             ((unsigned*)g_h1h)[idx - 77824] = 0u;
        if (idx == 0) { g_arr = 0u; g_epoch = 0u; }
        return;
    }
    if (bid < 4704) {
        int idx = (bid - 608) * 256 + t;         // TS*BT*32 = 1048576
        int i = idx & 31;
        int b = (idx >> 5) & 63;
        int tt = idx >> 11;
        float v = (i < 30) ? x[((size_t)b * TS + tt) * 30 + i] : 0.f;
        g_x16[idx] = __float2half_rn(v);
        return;
    }
    if (bid < 4817) {
        int idx = (bid - 4704) * 256 + t;        // 50*9*2*32 = 28800
        if (idx >= 28800) return;
        int lane = idx & 31;
        int kt = (idx >> 5) & 1;
        int u = idx >> 6;
        int s = u % 9;
        int cta = u / 9;
        int row = (s / 3) * 1200 + cta * 24 + (s % 3) * 8 + (lane >> 2);
        int k0 = (lane & 3) * 8 + kt * 4;
        unsigned h[4];
#pragma unroll
        for (int c = 0; c < 4; ++c) {
            int k = k0 + c;
            float v = (k < 30) ? Wih0[(size_t)row * 30 + k] : 0.f;
            h[c] = (unsigned)__half_as_ushort(__float2half_rn(v));
        }
        uint2 o; o.x = h[0] | (h[1] << 16); o.y = h[2] | (h[3] << 16);
        g_Wxp[idx] = o;
        return;
    }
    {
        long idx = (long)(bid - 4817) * 256 + t; // NCTA*12*76*32 = 4231680
        const long total = (long)NCTA * 12 * KTN * 32;
        if (idx >= total) return;
        int lane = (int)(idx & 31);
        long u = idx >> 5;
        int kt = (int)(u % KTN);
        long v = u / KTN;
        int s = (int)(v % 12);
        int cta = (int)(v / 12);
        const float* W;
        int row0;
        if (cta < 50) {
            if (s >= 9) return;
            W = Whh0; row0 = (s / 3) * 1200 + cta * 24 + (s % 3) * 8;
        } else if (cta < 95) {
            if (s >= 10) return;
            W = Wih1; row0 = ((cta - 50) * 10 + s) * 8;
        } else {
            if (s >= 9) return;
            W = Whh1; row0 = (s / 3) * 1200 + (cta - 95) * 24 + (s % 3) * 8;
        }
        int row = row0 + (lane >> 2);
        int k0 = (kt >> 1) * 32 + (lane & 3) * 8 + (kt & 1) * 4;
        unsigned h[4];
#pragma unroll
        for (int c = 0; c < 4; ++c) {
            int k = k0 + c;
            float vv = (k < 1200) ? W[(size_t)row * 1200 + k] : 0.f;
            h[c] = (unsigned)__half_as_ushort(__float2half_rn(vv));
        }
        uint2 o; o.x = h[0] | (h[1] << 16); o.y = h[2] | (h[3] << 16);
        g_Wpk[idx] = o;
    }
}

// ---------------- device helpers ----------------
__device__ __forceinline__ void mma_16816(float c[4],
    unsigned a0, unsigned a1, unsigned a2, unsigned a3, unsigned b0, unsigned b1) {
    asm volatile(
        "mma.sync.aligned.m16n8k16.row.col.f32.f16.f16.f32 "
        "{%0,%1,%2,%3},{%4,%5,%6,%7},{%8,%9},{%0,%1,%2,%3};"
        : "+f"(c[0]), "+f"(c[1]), "+f"(c[2]), "+f"(c[3])
        : "r"(a0), "r"(a1), "r"(a2), "r"(a3), "r"(b0), "r"(b1));
}
__device__ __forceinline__ void cpa16(void* s, const void* g) {
    unsigned sa = (unsigned)__cvta_generic_to_shared(s);
    asm volatile("cp.async.cg.shared.global [%0],[%1],16;" :: "r"(sa), "l"(g));
}
__device__ __forceinline__ void cp_commit() { asm volatile("cp.async.commit_group;"); }
template <int N> __device__ __forceinline__ void cp_wait() {
    asm volatile("cp.async.wait_group %0;" :: "n"(N));
}
__device__ __forceinline__ float sigf(float x) {
    return __fdividef(1.f, 1.f + __expf(-x));
}
__device__ __forceinline__ float tanhf_fast(float x) {
    return __fdividef(2.f, 1.f + __expf(-2.f * x)) - 1.f;
}

// A load: one LDG.128 per (mt,p) covers 2 k-tiles (one kchunk)
__device__ __forceinline__ void ldA128(uint4 (&d)[2][2], const char* aBase,
                                       int rowA0, int tid4, int kc, int rstride) {
#pragma unroll
    for (int mt = 0; mt < 2; ++mt)
#pragma unroll
        for (int p = 0; p < 2; ++p) {
            const char* ptr = aBase + (size_t)(rowA0 + mt * 16 + p * 8) * rstride
                              + kc * 64 + tid4 * 16;
            asm volatile("ld.global.cg.v4.u32 {%0,%1,%2,%3},[%4];"
                         : "=r"(d[mt][p].x), "=r"(d[mt][p].y),
                           "=r"(d[mt][p].z), "=r"(d[mt][p].w) : "l"(ptr));
        }
}

template<int NS>
__device__ __forceinline__ void slots128(const char* smB, int kt, int lane,
                                         const uint4 (&cu)[2][2], bool hi,
                                         float (&acc)[2][NS][4]) {
#pragma unroll
    for (int s = 0; s < NS; ++s) {
        uint2 w = *(const uint2*)(smB + s * SLOTB + kt * 256 + lane * 8);
#pragma unroll
        for (int mt = 0; mt < 2; ++mt) {
            unsigned a0 = hi ? cu[mt][0].z : cu[mt][0].x;
            unsigned a1 = hi ? cu[mt][1].z : cu[mt][1].x;
            unsigned a2 = hi ? cu[mt][0].w : cu[mt][0].y;
            unsigned a3 = hi ? cu[mt][1].w : cu[mt][1].y;
            mma_16816(acc[mt][s], a0, a1, a2, a3, w.x, w.y);
        }
    }
}

template<int NS>
__device__ __forceinline__ void run_kloop128(const char* aBase, const char* smB,
        int kc_lo, int kc_hi, int rowA0, int tid4, int lane, float (&acc)[2][NS][4]) {
    uint4 cur[2][2], nxt[2][2];
    ldA128(cur, aBase, rowA0, tid4, kc_lo, HPAD * 2);
#pragma unroll
    for (int mt = 0; mt < 2; ++mt)
#pragma unroll
        for (int p = 0; p < 2; ++p) nxt[mt][p] = cur[mt][p];
#pragma unroll 1
    for (int kc = kc_lo; kc < kc_hi; ++kc) {
        if (kc + 1 < kc_hi) ldA128(nxt, aBase, rowA0, tid4, kc + 1, HPAD * 2);
        slots128<NS>(smB, kc * 2,     lane, cur, false, acc);
        slots128<NS>(smB, kc * 2 + 1, lane, cur, true,  acc);
#pragma unroll
        for (int mt = 0; mt < 2; ++mt)
#pragma unroll
            for (int p = 0; p < 2; ++p) cur[mt][p] = nxt[mt][p];
    }
}

template<int NS>
__device__ __forceinline__ void writePB(__half* PBh, int grp, const float (&acc)[2][NS][4],
                                        int rowA0, int tid4) {
#pragma unroll
    for (int mt = 0; mt < 2; ++mt)
#pragma unroll
        for (int s = 0; s < NS; ++s)
#pragma unroll
            for (int p = 0; p < 2; ++p) {
                int b = rowA0 + mt * 16 + p * 8;
                __half2 v = __floats2half2_rn(acc[mt][s][p * 2], acc[mt][s][p * 2 + 1]);
                *(__half2*)(PBh + (grp * NS + s) * 512 + b * 8 + tid4 * 2) = v;
            }
}
template<int NS>
__device__ __forceinline__ void addPB(__half* PBh, int grp, float (&acc)[2][NS][4],
                                      int rowA0, int tid4) {
#pragma unroll
    for (int mt = 0; mt < 2; ++mt)
#pragma unroll
        for (int s = 0; s < NS; ++s)
#pragma unroll
            for (int p = 0; p < 2; ++p) {
                int b = rowA0 + mt * 16 + p * 8;
                __half2 u = *(__half2*)(PBh + (grp * NS + s) * 512 + b * 8 + tid4 * 2);
                acc[mt][s][p * 2]     += __low2float(u);
                acc[mt][s][p * 2 + 1] += __high2float(u);
            }
}

// ---------------- persistent kernel ----------------
__global__ void __launch_bounds__(NTH, 1) gru_main(
    const float* __restrict__ b_ih0, const float* __restrict__ b_hh0,
    const float* __restrict__ b_ih1, const float* __restrict__ b_hh1,
    float* __restrict__ out)
{
    extern __shared__ char sm[];
    const int cta  = blockIdx.x;
    const int tid  = threadIdx.x;
    const int wid  = tid >> 5;
    const int lane = tid & 31;
    const int mw   = wid >> 2;
    const int kw   = wid & 3;
    const int g    = lane >> 2;
    const int tid4 = lane & 3;
    const int cls  = (cta < 50) ? 0 : (cta < 95) ? 1 : 2;
    const int nbig = (cls == 1) ? 10 : 9;

    const int kc_lo = (kw == 0) ? 0 : (kw == 1) ? 9 : (kw == 2) ? 19 : 29;
    const int kc_hi = (kw == 0) ? 9 : (kw == 1) ? 19 : (kw == 2) ? 29 : 38;
    const int rowA0 = mw * 32 + g;

    // smem regions
    const int PB_off = (cls == 0) ? 179712 : (cls == 1) ? 194560 : 175104;
    __half* PBh = (__half*)(sm + PB_off);
    const int pbsz = 2 * nbig * 512 * 2;
    float*  pre  = (float*)(sm + PB_off + pbsz);      // L0: 12 slots; H1: 9 slots
    const int presz = ((cls == 0) ? 12 : 9) * 64 * 9 * 4;
    __half* hbuf = (__half*)((char*)pre + presz);     // 64*26 halves

    // ---- load resident weights ----
    {
        const uint2* wsrc = g_Wpk + (size_t)cta * 12 * KTN * 32;
        int n16 = nbig * 1216;                        // 16B units per slot = 19456/16
        for (int i = tid; i < n16; i += NTH)
            cpa16(sm + i * 16, wsrc + i * 2);
        if (cls == 0) {
            const uint2* xs = g_Wxp + cta * 576;
            for (int i = tid; i < 288; i += NTH)
                cpa16(sm + SM_XW + i * 16, xs + i * 2);
        }
        cp_commit();
        cp_wait<0>();
        __syncthreads();
    }

    // ---- combine-side setup ----
    const int jbase = (cls == 0) ? cta * 24 : (cls == 2) ? (cta - 95) * 24 : 0;
    float bias[6][4];
    float hprev[6];
    if (cls != 1) {
        const float* bi = (cls == 0) ? b_ih0 : b_ih1;
        const float* bh = (cls == 0) ? b_hh0 : b_hh1;
#pragma unroll
        for (int q = 0; q < 6; ++q) {
            int jg = jbase + ((q * 256 + tid) >> 6);
            bias[q][0] = __ldg(bi + jg) + __ldg(bh + jg);
            bias[q][1] = __ldg(bi + 1200 + jg) + __ldg(bh + 1200 + jg);
            bias[q][2] = __ldg(bi + 2400 + jg);
            bias[q][3] = __ldg(bh + 2400 + jg);
            hprev[q] = 0.f;
        }
    }

    for (int r = 0; r < ROUNDS; ++r) {
        const bool act = (cls == 0) ? (r < TS)
                        : (cls == 1) ? (r >= 1 && r <= TS)
                                     : (r >= 2);
        if (act) {
            if (cls == 1) {
                // ---------------- I1 ----------------
                float acc[2][10][4];
#pragma unroll
                for (int mt = 0; mt < 2; ++mt)
#pragma unroll
                    for (int s = 0; s < 10; ++s)
#pragma unroll
                        for (int c = 0; c < 4; ++c) acc[mt][s][c] = 0.f;

                const char* aBase = (const char*)g_h0h[(r + 1) & 1];
                run_kloop128<10>(aBase, sm, kc_lo, kc_hi, rowA0, tid4, lane, acc);

                if (kw == 1) writePB<10>(PBh, 0, acc, rowA0, tid4);
                if (kw == 3) writePB<10>(PBh, 1, acc, rowA0, tid4);
                __syncthreads();
                if (kw == 0) addPB<10>(PBh, 0, acc, rowA0, tid4);
                if (kw == 2) { addPB<10>(PBh, 1, acc, rowA0, tid4);
                               writePB<10>(PBh, 1, acc, rowA0, tid4); }
                __syncthreads();
                if (kw == 0) {
                    addPB<10>(PBh, 1, acc, rowA0, tid4);
                    float* gw = g_gi1[(r - 1) & 1];
#pragma unroll
                    for (int mt = 0; mt < 2; ++mt)
#pragma unroll
                        for (int s = 0; s < 10; ++s)
#pragma unroll
                            for (int p = 0; p < 2; ++p) {
                                int b = rowA0 + mt * 16 + p * 8;
                                int gr = ((cta - 50) * 10 + s) * 8 + tid4 * 2;
                                __stcg(gw + (size_t)gr * BT + b, acc[mt][s][p * 2]);
                                __stcg(gw + (size_t)(gr + 1) * BT + b, acc[mt][s][p * 2 + 1]);
                            }
                }
            } else {
                // ---------------- L0 / H1 ----------------
                float acc[2][9][4];
#pragma unroll
                for (int mt = 0; mt < 2; ++mt)
#pragma unroll
                    for (int s = 0; s < 9; ++s)
#pragma unroll
                        for (int c = 0; c < 4; ++c) acc[mt][s][c] = 0.f;

                const char* aBase = (cls == 2) ? (const char*)g_h1h[(r + 1) & 1]
                                               : (const char*)g_h0h[(r + 1) & 1];

                float accIN[2][3][4];
                if (cls == 0 && kw == 3) {
#pragma unroll
                    for (int mt = 0; mt < 2; ++mt)
#pragma unroll
                        for (int s = 0; s < 3; ++s)
#pragma unroll
                            for (int c = 0; c < 4; ++c) accIN[mt][s][c] = 0.f;
                    const char* xb = (const char*)g_x16 + (size_t)r * 4096;
                    uint4 xa[2][2];
                    ldA128(xa, xb, rowA0, tid4, 0, 64);
#pragma unroll
                    for (int s = 0; s < 9; ++s) {
                        uint2 w0 = *(const uint2*)(sm + SM_XW + (s * 2) * 256 + lane * 8);
                        uint2 w1 = *(const uint2*)(sm + SM_XW + (s * 2 + 1) * 256 + lane * 8);
#pragma unroll
                        for (int mt = 0; mt < 2; ++mt) {
                            float* tgt = (s < 6) ? acc[mt][s] : accIN[mt][s - 6];
                            mma_16816(tgt, xa[mt][0].x, xa[mt][1].x, xa[mt][0].y, xa[mt][1].y,
                                      w0.x, w0.y);
                            mma_16816(tgt, xa[mt][0].z, xa[mt][1].z, xa[mt][0].w, xa[mt][1].w,
                                      w1.x, w1.y);
                        }
                    }
                }

                run_kloop128<9>(aBase, sm, kc_lo, kc_hi, rowA0, tid4, lane, acc);

                float giPre[6][3];
                if (cls == 2) {
                    const float* gi = g_gi1[r & 1];
#pragma unroll
                    for (int q = 0; q < 6; ++q) {
                        int pi = q * 256 + tid;
                        int b = pi & 63, j = pi >> 6;
                        int jg = jbase + j;
                        giPre[q][0] = __ldcg(gi + (size_t)jg * BT + b);
                        giPre[q][1] = __ldcg(gi + (size_t)(1200 + jg) * BT + b);
                        giPre[q][2] = __ldcg(gi + (size_t)(2400 + jg) * BT + b);
                    }
                }

                if (kw == 1) writePB<9>(PBh, 0, acc, rowA0, tid4);
                if (kw == 3) {
                    writePB<9>(PBh, 1, acc, rowA0, tid4);
                    if (cls == 0) {
                        // i_n partials straight into pre slots 9..11 (fp32)
#pragma unroll
                        for (int mt = 0; mt < 2; ++mt)
#pragma unroll
                            for (int s = 0; s < 3; ++s)
#pragma unroll
                                for (int p = 0; p < 2; ++p) {
                                    int b = rowA0 + mt * 16 + p * 8;
                                    float* pp = pre + ((9 + s) * 64 + b) * 9 + tid4 * 2;
                                    pp[0] = accIN[mt][s][p * 2];
                                    pp[1] = accIN[mt][s][p * 2 + 1];
                                }
                    }
                }
                __syncthreads();
                if (kw == 0) addPB<9>(PBh, 0, acc, rowA0, tid4);
                if (kw == 2) { addPB<9>(PBh, 1, acc, rowA0, tid4);
                               writePB<9>(PBh, 1, acc, rowA0, tid4); }
                __syncthreads();
                if (kw == 0) {
                    addPB<9>(PBh, 1, acc, rowA0, tid4);
#pragma unroll
                    for (int mt = 0; mt < 2; ++mt)
#pragma unroll
                        for (int s = 0; s < 9; ++s)
#pragma unroll
                            for (int p = 0; p < 2; ++p) {
                                int b = rowA0 + mt * 16 + p * 8;
                                float* pp = pre + (s * 64 + b) * 9 + tid4 * 2;
                                pp[0] = acc[mt][s][p * 2];
                                pp[1] = acc[mt][s][p * 2 + 1];
                            }
                }
                __syncthreads();

                // ---- combine ----
                if (cls == 0) {
#pragma unroll
                    for (int q = 0; q < 6; ++q) {
                        int pi = q * 256 + tid;
                        int b = pi & 63, j = pi >> 6;
                        int sub = j >> 3, cl = j & 7;
                        float pR  = pre[((sub) * 64 + b) * 9 + cl];
                        float pZ  = pre[((3 + sub) * 64 + b) * 9 + cl];
                        float pHN = pre[((6 + sub) * 64 + b) * 9 + cl];
                        float pIN = pre[((9 + sub) * 64 + b) * 9 + cl];
                        float vr = sigf(pR + bias[q][0]);
                        float vz = sigf(pZ + bias[q][1]);
                        float vn = tanhf_fast(pIN + bias[q][2] + vr * (pHN + bias[q][3]));
                        float h = vn + vz * (hprev[q] - vn);
                        hprev[q] = h;
                        hbuf[b * 26 + j] = __float2half_rn(h);
                        if (r == TS - 1) out[(size_t)b * HIDN + jbase + j] = h;
                    }
                } else {
#pragma unroll
                    for (int q = 0; q < 6; ++q) {
                        int pi = q * 256 + tid;
                        int b = pi & 63, j = pi >> 6;
                        int sub = j >> 3, cl = j & 7;
                        float pR  = pre[((sub) * 64 + b) * 9 + cl];
                        float pZ  = pre[((3 + sub) * 64 + b) * 9 + cl];
                        float pHN = pre[((6 + sub) * 64 + b) * 9 + cl];
                        float vr = sigf(giPre[q][0] + pR + bias[q][0]);
                        float vz = sigf(giPre[q][1] + pZ + bias[q][1]);
                        float vn = tanhf_fast(giPre[q][2] + bias[q][2] + vr * (pHN + bias[q][3]));
                        float h = vn + vz * (hprev[q] - vn);
                        hprev[q] = h;
                        hbuf[b * 26 + j] = __float2half_rn(h);
                        if (r == TS + 1) out[76800 + (size_t)b * HIDN + jbase + j] = h;
                    }
                }
                __syncthreads();
                {
                    __half* dstH = (cls == 0) ? g_h0h[r & 1] : g_h1h[r & 1];
                    const unsigned* hb32 = (const unsigned*)hbuf;
#pragma unroll
                    for (int k = 0; k < 3; ++k) {
                        int idx = tid + k * 256;
                        int row = idx / 12, c = idx % 12;
                        unsigned v = hb32[row * 13 + c];
                        asm volatile("st.global.cg.u32 [%0], %1;"
                                     :: "l"(dstH + (size_t)row * HPAD + jbase + c * 2),
                                        "r"(v) : "memory");
                    }
                }
            }
        }

        // ---- grid barrier: tid0-only poll ----
        __threadfence();
        __syncthreads();
        if (tid == 0) {
            unsigned a = atomicAdd(&g_arr, 1u);
            if (a == NCTA - 1) {
                g_arr = 0u;
                __threadfence();
                atomicExch(&g_epoch, (unsigned)(r + 1));
            } else {
                unsigned e;
                int slp = 16;
                while (true) {
                    asm volatile("ld.global.cg.u32 %0,[%1];" : "=r"(e) : "l"(&g_epoch));
                    if (e >= (unsigned)(r + 1)) break;
                    __nanosleep(slp);
                    if (slp < 128) slp += slp;
                }
                __threadfence();
            }
        }
        __syncthreads();
    }
}

// ---------------- launch ----------------
extern "C" void kernel_launch(void* const* d_in, const int* in_sizes, int n_in,
                              void* d_out, int out_size) {
    const float* x     = (const float*)d_in[0];
    const float* W_ih0 = (const float*)d_in[1];
    const float* W_hh0 = (const float*)d_in[2];
    const float* b_ih0 = (const float*)d_in[3];
    const float* b_hh0 = (const float*)d_in[4];
    const float* W_ih1 = (const float*)d_in[5];
    const float* W_hh1 = (const float*)d_in[6];
    const float* b_ih1 = (const float*)d_in[7];
    const float* b_hh1 = (const float*)d_in[8];
    float* out = (float*)d_out;

    cudaFuncSetAttribute(gru_main,
                         cudaFuncAttributeMaxDynamicSharedMemorySize, SMEM_TOTAL);

    prep_all<<<21347, 256>>>(x, W_ih0, W_hh0, W_ih1, W_hh1);
    gru_main<<<NCTA, NTH, SMEM_TOTAL>>>(b_ih0, b_hh0, b_ih1, b_hh1, out);
}